// round 12
// baseline (speedup 1.0000x reference)
#include <cuda_runtime.h>
#include <cuda_fp16.h>
#include <math.h>
#include <stdint.h>

#define BB 2
#define CC 64
#define HH 128
#define WW 160
#define DD 16
#define VV 4
#define NV 9
#define HWP (HH*WW)

// ---------------- scratch (static device memory; no allocation) ----------------
__device__ __align__(16) __half g_srcT[(size_t)VV*BB*HWP*CC]; // fp16 [v*B+b][hw][c]
__device__ __align__(16) __half g_refT[(size_t)BB*HWP*CC];    // fp16 [b][hw][c]
__device__ float g_proj[VV*BB*12];
__device__ __align__(16) float g_s[(size_t)BB*HWP*DD];        // s channels-last [b][hw][d]

#define BNS 0.9999950000374997f

// ---------------- K0: transpose [C,HW] -> [HW,C] (fp16 staging) + fused proj ----------------
__global__ void k_transpose(const float* __restrict__ ref, const float* __restrict__ src,
                            const float* __restrict__ ref_proj, const float* __restrict__ src_projs) {
    int img = blockIdx.y;          // 0..7 = src v*B+b, 8..9 = ref b, 10 = proj
    if (img == VV*BB + BB) {
        if (blockIdx.x != 0) return;
        int t = threadIdx.x;
        if (t >= VV*BB) return;
        int v = t / BB, b = t % BB;
        float a[4][4], inv[4][4];
        #pragma unroll
        for (int i = 0; i < 4; i++)
            #pragma unroll
            for (int j = 0; j < 4; j++) {
                a[i][j] = ref_proj[b*16 + i*4 + j];
                inv[i][j] = (i == j) ? 1.f : 0.f;
            }
        for (int col = 0; col < 4; col++) {
            int piv = col; float best = fabsf(a[col][col]);
            for (int r = col+1; r < 4; r++) { float av = fabsf(a[r][col]); if (av > best) { best = av; piv = r; } }
            if (piv != col) {
                for (int j = 0; j < 4; j++) {
                    float tm = a[col][j]; a[col][j] = a[piv][j]; a[piv][j] = tm;
                    tm = inv[col][j]; inv[col][j] = inv[piv][j]; inv[piv][j] = tm;
                }
            }
            float dsc = 1.f / a[col][col];
            for (int j = 0; j < 4; j++) { a[col][j] *= dsc; inv[col][j] *= dsc; }
            for (int r = 0; r < 4; r++) {
                if (r == col) continue;
                float f = a[r][col];
                for (int j = 0; j < 4; j++) { a[r][j] -= f*a[col][j]; inv[r][j] -= f*inv[col][j]; }
            }
        }
        const float* s = src_projs + (size_t)(v*BB + b)*16;
        float* o = g_proj + (v*BB + b)*12;
        for (int i = 0; i < 3; i++)
            for (int j = 0; j < 4; j++) {
                float acc = 0.f;
                for (int k = 0; k < 4; k++) acc += s[i*4 + k] * inv[k][j];
                o[i*4 + j] = acc;
            }
        return;
    }
    __shared__ __half tile[64][72];   // fp16 staging, stride 72 halves (144B)
    int hw0 = blockIdx.x * 64;
    int tid = threadIdx.x;
    const float* in = (img < VV*BB) ? (src + (size_t)img*CC*HWP)
                                    : (ref + (size_t)(img - VV*BB)*CC*HWP);
    // load: 64c x 64hw tile as 1024 float4 (vectorized along hw), convert to fp16
    #pragma unroll
    for (int k = tid; k < 1024; k += 256) {
        int c   = k >> 4;     // 0..63
        int hw4 = k & 15;     // 0..15
        float4 v = *(const float4*)(in + (size_t)c*HWP + hw0 + hw4*4);
        tile[hw4*4+0][c] = __float2half_rn(v.x);
        tile[hw4*4+1][c] = __float2half_rn(v.y);
        tile[hw4*4+2][c] = __float2half_rn(v.z);
        tile[hw4*4+3][c] = __float2half_rn(v.w);
    }
    __syncthreads();
    __half* outh = (img < VV*BB)
        ? (g_srcT + (size_t)img*HWP*CC)
        : (g_refT + (size_t)(img - VV*BB)*HWP*CC);
    // write: 1024 uint2 (4 fp16 channels each), raw copy from shared
    #pragma unroll
    for (int k = tid; k < 1024; k += 256) {
        int hwl = k >> 4;     // 0..63
        int cp4 = k & 15;     // 0..15 (4 channels each)
        uint2 val = *(const uint2*)&tile[hwl][cp4*4];
        *(uint2*)(outh + (size_t)(hw0+hwl)*CC + cp4*4) = val;
    }
}

// ---------------- fp16 packed MLP (8 -> 16 -> 8 -> 1) ----------------
__device__ __forceinline__ __half2 u2h(uint32_t u) { return *reinterpret_cast<__half2*>(&u); }

__device__ __forceinline__ float mlp8h(const uint32_t* __restrict__ swh, const float in8[8]) {
    __half2 ind[8];
    #pragma unroll
    for (int g = 0; g < 8; g++) ind[g] = __float2half2_rn(in8[g]);
    const uint4* W0 = (const uint4*)swh;
    const uint4* W1 = (const uint4*)(swh + 80);
    const __half2 zero = __float2half2_rn(0.f);
    __half2 h1[8];
    #pragma unroll
    for (int jp = 0; jp < 8; jp++) {
        uint4 wa = W0[jp*2], wb = W0[jp*2+1];
        __half2 acc = __hmul2(u2h(wa.x), ind[0]);
        acc = __hfma2(u2h(wa.y), ind[1], acc);
        acc = __hfma2(u2h(wa.z), ind[2], acc);
        acc = __hfma2(u2h(wa.w), ind[3], acc);
        acc = __hfma2(u2h(wb.x), ind[4], acc);
        acc = __hfma2(u2h(wb.y), ind[5], acc);
        acc = __hfma2(u2h(wb.z), ind[6], acc);
        acc = __hfma2(u2h(wb.w), ind[7], acc);
        acc = __hfma2(acc, u2h(swh[64 + jp]), u2h(swh[72 + jp]));
        h1[jp] = __hmax2(acc, zero);
    }
    __half2 hd[16];
    #pragma unroll
    for (int jp = 0; jp < 8; jp++) {
        hd[2*jp]   = __low2half2(h1[jp]);
        hd[2*jp+1] = __high2half2(h1[jp]);
    }
    __half2 oacc = zero;
    #pragma unroll
    for (int kp = 0; kp < 4; kp++) {
        uint4 w0v = W1[kp*4], w1v = W1[kp*4+1], w2v = W1[kp*4+2], w3v = W1[kp*4+3];
        __half2 acc = __hmul2(u2h(w0v.x), hd[0]);
        acc = __hfma2(u2h(w0v.y), hd[1], acc);
        acc = __hfma2(u2h(w0v.z), hd[2], acc);
        acc = __hfma2(u2h(w0v.w), hd[3], acc);
        acc = __hfma2(u2h(w1v.x), hd[4], acc);
        acc = __hfma2(u2h(w1v.y), hd[5], acc);
        acc = __hfma2(u2h(w1v.z), hd[6], acc);
        acc = __hfma2(u2h(w1v.w), hd[7], acc);
        acc = __hfma2(u2h(w2v.x), hd[8], acc);
        acc = __hfma2(u2h(w2v.y), hd[9], acc);
        acc = __hfma2(u2h(w2v.z), hd[10], acc);
        acc = __hfma2(u2h(w2v.w), hd[11], acc);
        acc = __hfma2(u2h(w3v.x), hd[12], acc);
        acc = __hfma2(u2h(w3v.y), hd[13], acc);
        acc = __hfma2(u2h(w3v.z), hd[14], acc);
        acc = __hfma2(u2h(w3v.w), hd[15], acc);
        acc = __hfma2(acc, u2h(swh[144 + kp]), u2h(swh[148 + kp]));
        acc = __hmax2(acc, zero);
        oacc = __hfma2(u2h(swh[152 + kp]), acc, oacc);
    }
    float2 of = __half22float2(oacc);
    return of.x + of.y + __uint_as_float(swh[156]);
}

// ---------------- K2: warp + group correlation + pixelwise net + similarity net ----------------
// block = 128 threads = 8 pixels × 16 lanes; lane = (dh, g).
__global__ void __launch_bounds__(128)
k_main(const float* __restrict__ depth_sample,
       const float* __restrict__ pw_w0, const float* __restrict__ pw_g0, const float* __restrict__ pw_b0,
       const float* __restrict__ pw_w1, const float* __restrict__ pw_g1, const float* __restrict__ pw_b1,
       const float* __restrict__ pw_w2, const float* __restrict__ pw_c2b,
       const float* __restrict__ sn_w0, const float* __restrict__ sn_g0, const float* __restrict__ sn_b0,
       const float* __restrict__ sn_w1, const float* __restrict__ sn_g1, const float* __restrict__ sn_b1,
       const float* __restrict__ sn_w2, const float* __restrict__ sn_c2b,
       float* __restrict__ out_vw) {
    __shared__ __align__(16) uint32_t swh[2][160];
    __shared__ __align__(16) uint32_t scoord[8][16][6]; // packed coords, stride 6 words
    __shared__ uint32_t simh [8][16][5];  // [pix][d][4 half2 + pad]; stride 5

    int tid = threadIdx.x;

    // pack fp16 MLP weights
    for (int i = tid; i < 320; i += 128) {
        int net = i / 160, j = i - net*160;
        const float* w0 = net ? sn_w0 : pw_w0;
        const float* g0 = net ? sn_g0 : pw_g0;
        const float* b0 = net ? sn_b0 : pw_b0;
        const float* w1 = net ? sn_w1 : pw_w1;
        const float* g1 = net ? sn_g1 : pw_g1;
        const float* b1 = net ? sn_b1 : pw_b1;
        const float* w2 = net ? sn_w2 : pw_w2;
        const float* cb = net ? sn_c2b : pw_c2b;
        uint32_t val;
        if (j < 64) {
            int jp = j >> 3, g = j & 7;
            __half2 h = __floats2half2_rn(w0[(2*jp)*8 + g], w0[(2*jp+1)*8 + g]);
            val = *reinterpret_cast<uint32_t*>(&h);
        } else if (j < 72) {
            int jp = j - 64;
            __half2 h = __floats2half2_rn(g0[2*jp]*BNS, g0[2*jp+1]*BNS);
            val = *reinterpret_cast<uint32_t*>(&h);
        } else if (j < 80) {
            int jp = j - 72;
            __half2 h = __floats2half2_rn(b0[2*jp], b0[2*jp+1]);
            val = *reinterpret_cast<uint32_t*>(&h);
        } else if (j < 144) {
            int idx = j - 80; int kp = idx >> 4, jj = idx & 15;
            __half2 h = __floats2half2_rn(w1[(2*kp)*16 + jj], w1[(2*kp+1)*16 + jj]);
            val = *reinterpret_cast<uint32_t*>(&h);
        } else if (j < 148) {
            int kp = j - 144;
            __half2 h = __floats2half2_rn(g1[2*kp]*BNS, g1[2*kp+1]*BNS);
            val = *reinterpret_cast<uint32_t*>(&h);
        } else if (j < 152) {
            int kp = j - 148;
            __half2 h = __floats2half2_rn(b1[2*kp], b1[2*kp+1]);
            val = *reinterpret_cast<uint32_t*>(&h);
        } else if (j < 156) {
            int kp = j - 152;
            __half2 h = __floats2half2_rn(w2[2*kp], w2[2*kp+1]);
            val = *reinterpret_cast<uint32_t*>(&h);
        } else {
            val = __float_as_uint(cb[0]);
        }
        swh[net][j] = val;
    }
    __syncthreads();

    int pix  = tid >> 4;         // 0..7 within block (2 pixels per warp)
    int lane = tid & 15;         // 0..15: owned depth
    int dh   = lane >> 3;        // depth-half for Phase B
    int g    = lane & 7;         // group for Phase B
    int p = blockIdx.x * 8 + pix;
    int b  = p / HWP;
    int hw = p - b * HWP;
    int h = hw / WW, w = hw - h * WW;
    float wf = (float)w, hf = (float)h;

    // ref features for group g (8 channels fp16 = one uint4)
    uint4 ru = __ldg((const uint4*)(g_refT + (size_t)p*CC) + g);
    __half2 rh0 = u2h(ru.x), rh1 = u2h(ru.y), rh2 = u2h(ru.z), rh3 = u2h(ru.w);

    // depth owned by this lane
    float myDep = __ldg(depth_sample + (size_t)b*DD*HWP + (size_t)lane*HWP + hw);

    float acc[8];
    #pragma unroll
    for (int k = 0; k < 8; k++) acc[k] = 0.f;
    float wsum = 0.f;

    for (int v = 0; v < VV; v++) {
        const float* M = g_proj + (v*BB + b)*12;
        float rx = M[0]*wf + M[1]*hf + M[2];
        float ry = M[4]*wf + M[5]*hf + M[6];
        float rz = M[8]*wf + M[9]*hf + M[10];
        float t0 = M[3], t1 = M[7], t2 = M[11];
        const __half* srcB = g_srcT + (size_t)(v*BB + b)*HWP*CC;

        // ---- Phase A: coords for owned depth (packed to 4 words) ----
        {
            float px = rx*myDep + t0, py = ry*myDep + t1, pz = rz*myDep + t2;
            if (pz <= 0.001f) { px = (float)WW; py = (float)HH; pz = 1.f; }
            float ix = __fdividef(px, pz);
            float iy = __fdividef(py, pz);
            float x0f = floorf(ix), y0f = floorf(iy);
            float fx = ix - x0f, fy = iy - y0f;
            int x0 = (int)x0f, y0 = (int)y0f;
            int x1 = x0 + 1, y1 = y0 + 1;
            bool vx0 = (x0 >= 0) & (x0 < WW);
            bool vx1 = (x1 >= 0) & (x1 < WW);
            bool vy0 = (y0 >= 0) & (y0 < HH);
            bool vy1 = (y1 >= 0) & (y1 < HH);
            float w00 = (1.f-fx)*(1.f-fy) * (float)(vx0 && vy0);
            float w01 = fx*(1.f-fy)       * (float)(vx1 && vy0);
            float w10 = (1.f-fx)*fy       * (float)(vx0 && vy1);
            float w11 = fx*fy             * (float)(vx1 && vy1);
            int xc0 = min(max(x0, 0), WW-1), xc1 = min(max(x1, 0), WW-1);
            int yc0 = min(max(y0, 0), HH-1), yc1 = min(max(y1, 0), HH-1);
            int r0 = yc0*WW, r1 = yc1*WW;
            uint32_t i00 = (uint32_t)(r0 + xc0), i01 = (uint32_t)(r0 + xc1);
            uint32_t i10 = (uint32_t)(r1 + xc0), i11 = (uint32_t)(r1 + xc1);
            __half2 hw01 = __floats2half2_rn(w00, w01);
            __half2 hw23 = __floats2half2_rn(w10, w11);
            uint32_t* sc = scoord[pix][lane];
            *(uint2*)&sc[0] = make_uint2(i00 | (i01 << 16), i10 | (i11 << 16));
            *(uint2*)&sc[2] = make_uint2(*reinterpret_cast<uint32_t*>(&hw01),
                                         *reinterpret_cast<uint32_t*>(&hw23));
        }
        __syncwarp();

        // ---- Phase B: 8 depths per lane (lane = dh half, group g) ----
        #pragma unroll
        for (int dl = 0; dl < 8; dl++) {
            int d = dh*8 + dl;
            uint2 ia = *(const uint2*)&scoord[pix][d][0];
            uint2 wv = *(const uint2*)&scoord[pix][d][2];
            uint32_t i00 = ia.x & 0xFFFFu, i01 = ia.x >> 16;
            uint32_t i10 = ia.y & 0xFFFFu, i11 = ia.y >> 16;
            __half2 pw01 = u2h(wv.x), pw23 = u2h(wv.y);
            __half2 w00 = __low2half2(pw01),  w01 = __high2half2(pw01);
            __half2 w10 = __low2half2(pw23),  w11 = __high2half2(pw23);
            uint4 u00 = __ldg((const uint4*)(srcB + (size_t)i00*CC) + g);
            uint4 u01 = __ldg((const uint4*)(srcB + (size_t)i01*CC) + g);
            uint4 u10 = __ldg((const uint4*)(srcB + (size_t)i10*CC) + g);
            uint4 u11 = __ldg((const uint4*)(srcB + (size_t)i11*CC) + g);
            __half2 m0 = __hmul2(u2h(u00.x), w00);
            __half2 m1 = __hmul2(u2h(u00.y), w00);
            __half2 m2 = __hmul2(u2h(u00.z), w00);
            __half2 m3 = __hmul2(u2h(u00.w), w00);
            m0 = __hfma2(u2h(u01.x), w01, m0);
            m1 = __hfma2(u2h(u01.y), w01, m1);
            m2 = __hfma2(u2h(u01.z), w01, m2);
            m3 = __hfma2(u2h(u01.w), w01, m3);
            m0 = __hfma2(u2h(u10.x), w10, m0);
            m1 = __hfma2(u2h(u10.y), w10, m1);
            m2 = __hfma2(u2h(u10.z), w10, m2);
            m3 = __hfma2(u2h(u10.w), w10, m3);
            m0 = __hfma2(u2h(u11.x), w11, m0);
            m1 = __hfma2(u2h(u11.y), w11, m1);
            m2 = __hfma2(u2h(u11.z), w11, m2);
            m3 = __hfma2(u2h(u11.w), w11, m3);
            __half2 da = __hmul2(m0, rh0);
            da = __hfma2(m1, rh1, da);
            da = __hfma2(m2, rh2, da);
            da = __hfma2(m3, rh3, da);
            float2 df = __half22float2(da);
            ((__half*)&simh[pix][d][0])[g] = __float2half_rn((df.x + df.y) * 0.125f);
        }
        __syncwarp();

        // ---- pixelwise net: lane owns depth = lane ----
        const uint32_t* sv = simh[pix][lane];
        float in8[8];
        {
            float2 a0 = __half22float2(u2h(sv[0]));
            float2 a1 = __half22float2(u2h(sv[1]));
            float2 a2 = __half22float2(u2h(sv[2]));
            float2 a3 = __half22float2(u2h(sv[3]));
            in8[0]=a0.x; in8[1]=a0.y; in8[2]=a1.x; in8[3]=a1.y;
            in8[4]=a2.x; in8[5]=a2.y; in8[6]=a3.x; in8[7]=a3.y;
        }
        float o = mlp8h(swh[0], in8);
        float vwv = __frcp_rn(1.f + __expf(-o));
        #pragma unroll
        for (int k = 8; k >= 1; k >>= 1)
            vwv = fmaxf(vwv, __shfl_xor_sync(0xffffffffu, vwv, k, 16));
        #pragma unroll
        for (int k = 0; k < 8; k++) acc[k] += in8[k]*vwv;
        wsum += vwv;
        if (lane == 0) out_vw[((size_t)b*VV + v)*HWP + hw] = vwv;
        __syncwarp();
    }

    float rws = 1.f / wsum;
    float in8[8];
    #pragma unroll
    for (int k = 0; k < 8; k++) in8[k] = acc[k]*rws;
    float sval = mlp8h(swh[1], in8);
    g_s[(size_t)p*DD + lane] = sval;
}

// ---------------- K3: grid-sample + NN aggregation + softmax + depth ----------------
// 4 threads per pixel; thread q owns depths [4q, 4q+4)
__global__ void __launch_bounds__(128)
k_final(const float* __restrict__ grid, const float* __restrict__ weight,
        const float* __restrict__ depth_sample, const int* __restrict__ is_inverse,
        float* __restrict__ out_depth, float* __restrict__ out_score) {
    int t = blockIdx.x * blockDim.x + threadIdx.x;
    int p = t >> 2;
    int q = t & 3;
    if (p >= BB*HWP) return;
    int b  = p / HWP;
    int hw = p - b * HWP;
    int h = hw / WW, w = hw - h * WW;

    float agg[4] = {0.f, 0.f, 0.f, 0.f};

    const float* wbase = weight + ((size_t)b*DD*NV)*HWP + hw + (size_t)(q*4)*NV*HWP;
    #pragma unroll
    for (int n = 0; n < NV; n++) {
        const float* gp = grid + (((size_t)b*NV*HH + n*HH + h)*WW + w)*2;
        float gx = __ldg(gp), gy = __ldg(gp + 1);
        float ix = ((gx + 1.f)*WW - 1.f) * 0.5f;
        float iy = ((gy + 1.f)*HH - 1.f) * 0.5f;
        float x0f = floorf(ix), y0f = floorf(iy);
        float fx = ix - x0f, fy = iy - y0f;
        int x0 = (int)x0f, y0 = (int)y0f;
        int xc0 = min(max(x0, 0), WW-1), xc1 = min(max(x0+1, 0), WW-1);
        int yc0 = min(max(y0, 0), HH-1), yc1 = min(max(y0+1, 0), HH-1);
        float w00 = (1.f-fx)*(1.f-fy), w01 = fx*(1.f-fy);
        float w10 = (1.f-fx)*fy,       w11 = fx*fy;
        float4 a00 = __ldg((const float4*)(g_s + ((size_t)b*HWP + yc0*WW + xc0)*DD) + q);
        float4 a01 = __ldg((const float4*)(g_s + ((size_t)b*HWP + yc0*WW + xc1)*DD) + q);
        float4 a10 = __ldg((const float4*)(g_s + ((size_t)b*HWP + yc1*WW + xc0)*DD) + q);
        float4 a11 = __ldg((const float4*)(g_s + ((size_t)b*HWP + yc1*WW + xc1)*DD) + q);
        float bx = w00*a00.x + w01*a01.x + w10*a10.x + w11*a11.x;
        float by = w00*a00.y + w01*a01.y + w10*a10.y + w11*a11.y;
        float bz = w00*a00.z + w01*a01.z + w10*a10.z + w11*a11.z;
        float bw = w00*a00.w + w01*a01.w + w10*a10.w + w11*a11.w;
        const float* wb = wbase + (size_t)n*HWP;
        agg[0] += __ldg(wb)                      * bx;
        agg[1] += __ldg(wb + (size_t)1*NV*HWP)   * by;
        agg[2] += __ldg(wb + (size_t)2*NV*HWP)   * bz;
        agg[3] += __ldg(wb + (size_t)3*NV*HWP)   * bw;
    }

    float m = fmaxf(fmaxf(agg[0], agg[1]), fmaxf(agg[2], agg[3]));
    m = fmaxf(m, __shfl_xor_sync(0xffffffffu, m, 1, 4));
    m = fmaxf(m, __shfl_xor_sync(0xffffffffu, m, 2, 4));
    float e[4]; float sum = 0.f;
    #pragma unroll
    for (int j = 0; j < 4; j++) { e[j] = __expf(agg[j] - m); sum += e[j]; }
    sum += __shfl_xor_sync(0xffffffffu, sum, 1, 4);
    sum += __shfl_xor_sync(0xffffffffu, sum, 2, 4);
    float rs = 1.f / sum;

    const float* dsB = depth_sample + (size_t)b*DD*HWP + hw;
    float dep = 0.f;
    int inv = *is_inverse;
    #pragma unroll
    for (int j = 0; j < 4; j++) {
        float sc = e[j] * rs;
        int d = q*4 + j;
        out_score[((size_t)b*DD + d)*HWP + hw] = sc;
        if (inv) dep += (float)d * sc;
        else     dep += __ldg(dsB + (size_t)d*HWP) * sc;
    }
    dep += __shfl_xor_sync(0xffffffffu, dep, 1, 4);
    dep += __shfl_xor_sync(0xffffffffu, dep, 2, 4);
    if (q == 0) {
        if (inv) {
            float invmin = 1.f / __ldg(dsB + (size_t)(DD-1)*HWP);
            float invmax = 1.f / __ldg(dsB);
            dep = 1.f / (invmax + dep * (1.f/(float)(DD-1)) * (invmin - invmax));
        }
        out_depth[p] = dep;
    }
}

// ---------------- launch ----------------
extern "C" void kernel_launch(void* const* d_in, const int* in_sizes, int n_in,
                              void* d_out, int out_size) {
    const float* ref_feature  = (const float*)d_in[0];
    const float* src_features = (const float*)d_in[1];
    const float* ref_proj     = (const float*)d_in[2];
    const float* src_projs    = (const float*)d_in[3];
    const float* depth_sample = (const float*)d_in[4];
    const float* grid         = (const float*)d_in[5];
    const float* weight       = (const float*)d_in[6];
    const float* pw_w0  = (const float*)d_in[7];
    const float* pw_g0  = (const float*)d_in[8];
    const float* pw_b0  = (const float*)d_in[9];
    const float* pw_w1  = (const float*)d_in[10];
    const float* pw_g1  = (const float*)d_in[11];
    const float* pw_b1  = (const float*)d_in[12];
    const float* pw_w2  = (const float*)d_in[13];
    const float* pw_c2b = (const float*)d_in[14];
    const float* sn_w0  = (const float*)d_in[15];
    const float* sn_g0  = (const float*)d_in[16];
    const float* sn_b0  = (const float*)d_in[17];
    const float* sn_w1  = (const float*)d_in[18];
    const float* sn_g1  = (const float*)d_in[19];
    const float* sn_b1  = (const float*)d_in[20];
    const float* sn_w2  = (const float*)d_in[21];
    const float* sn_c2b = (const float*)d_in[22];
    const int*   is_inv = (const int*)d_in[23];

    float* out       = (float*)d_out;
    float* out_depth = out;
    float* out_score = out + (size_t)BB*HWP;
    float* out_vw    = out + (size_t)BB*HWP + (size_t)BB*DD*HWP;

    k_transpose<<<dim3(HWP/64, VV*BB + BB + 1), 256>>>(ref_feature, src_features,
                                                       ref_proj, src_projs);
    k_main<<<BB*HWP/8, 128>>>(depth_sample,
                              pw_w0, pw_g0, pw_b0, pw_w1, pw_g1, pw_b1, pw_w2, pw_c2b,
                              sn_w0, sn_g0, sn_b0, sn_w1, sn_g1, sn_b1, sn_w2, sn_c2b,
                              out_vw);
    k_final<<<(BB*HWP*4 + 127)/128, 128>>>(grid, weight, depth_sample, is_inv,
                                           out_depth, out_score);
}

// round 13
// speedup vs baseline: 1.0286x; 1.0286x over previous
#include <cuda_runtime.h>
#include <cuda_fp16.h>
#include <math.h>
#include <stdint.h>

#define BB 2
#define CC 64
#define HH 128
#define WW 160
#define DD 16
#define VV 4
#define NV 9
#define HWP (HH*WW)

#define KM_PIX 16                 // pixels per k_main block
#define KM_THREADS (KM_PIX*16)    // 256

// ---------------- scratch (static device memory; no allocation) ----------------
__device__ __align__(16) __half g_srcT[(size_t)VV*BB*HWP*CC]; // fp16 [v*B+b][hw][c]
__device__ __align__(16) __half g_refT[(size_t)BB*HWP*CC];    // fp16 [b][hw][c]
__device__ float g_proj[VV*BB*12];
__device__ __align__(16) float g_s[(size_t)BB*HWP*DD];        // s channels-last [b][hw][d]

#define BNS 0.9999950000374997f

// ---------------- K0: transpose [C,HW] -> [HW,C] (fp32 staging, vectorized) + fused proj ----------------
__global__ void k_transpose(const float* __restrict__ ref, const float* __restrict__ src,
                            const float* __restrict__ ref_proj, const float* __restrict__ src_projs) {
    int img = blockIdx.y;          // 0..7 = src v*B+b, 8..9 = ref b, 10 = proj
    if (img == VV*BB + BB) {
        if (blockIdx.x != 0) return;
        int t = threadIdx.x;
        if (t >= VV*BB) return;
        int v = t / BB, b = t % BB;
        float a[4][4], inv[4][4];
        #pragma unroll
        for (int i = 0; i < 4; i++)
            #pragma unroll
            for (int j = 0; j < 4; j++) {
                a[i][j] = ref_proj[b*16 + i*4 + j];
                inv[i][j] = (i == j) ? 1.f : 0.f;
            }
        for (int col = 0; col < 4; col++) {
            int piv = col; float best = fabsf(a[col][col]);
            for (int r = col+1; r < 4; r++) { float av = fabsf(a[r][col]); if (av > best) { best = av; piv = r; } }
            if (piv != col) {
                for (int j = 0; j < 4; j++) {
                    float tm = a[col][j]; a[col][j] = a[piv][j]; a[piv][j] = tm;
                    tm = inv[col][j]; inv[col][j] = inv[piv][j]; inv[piv][j] = tm;
                }
            }
            float dsc = 1.f / a[col][col];
            for (int j = 0; j < 4; j++) { a[col][j] *= dsc; inv[col][j] *= dsc; }
            for (int r = 0; r < 4; r++) {
                if (r == col) continue;
                float f = a[r][col];
                for (int j = 0; j < 4; j++) { a[r][j] -= f*a[col][j]; inv[r][j] -= f*inv[col][j]; }
            }
        }
        const float* s = src_projs + (size_t)(v*BB + b)*16;
        float* o = g_proj + (v*BB + b)*12;
        for (int i = 0; i < 3; i++)
            for (int j = 0; j < 4; j++) {
                float acc = 0.f;
                for (int k = 0; k < 4; k++) acc += s[i*4 + k] * inv[k][j];
                o[i*4 + j] = acc;
            }
        return;
    }
    __shared__ float tile[64][65];
    int hw0 = blockIdx.x * 64;
    int tid = threadIdx.x;
    const float* in = (img < VV*BB) ? (src + (size_t)img*CC*HWP)
                                    : (ref + (size_t)(img - VV*BB)*CC*HWP);
    // load: 64c x 64hw tile as 1024 float4 (vectorized along hw)
    #pragma unroll
    for (int k = tid; k < 1024; k += 256) {
        int c   = k >> 4;     // 0..63
        int hw4 = k & 15;     // 0..15
        float4 v = *(const float4*)(in + (size_t)c*HWP + hw0 + hw4*4);
        tile[hw4*4+0][c] = v.x;
        tile[hw4*4+1][c] = v.y;
        tile[hw4*4+2][c] = v.z;
        tile[hw4*4+3][c] = v.w;
    }
    __syncthreads();
    __half* outh = (img < VV*BB)
        ? (g_srcT + (size_t)img*HWP*CC)
        : (g_refT + (size_t)(img - VV*BB)*HWP*CC);
    // write: 1024 uint2 (4 fp16 channels each)
    #pragma unroll
    for (int k = tid; k < 1024; k += 256) {
        int hwl = k >> 4;     // 0..63
        int cp4 = k & 15;     // 0..15 (4 channels each)
        const float* tr = &tile[hwl][cp4*4];
        __half2 p0 = __floats2half2_rn(tr[0], tr[1]);
        __half2 p1 = __floats2half2_rn(tr[2], tr[3]);
        uint2 val = make_uint2(*reinterpret_cast<uint32_t*>(&p0),
                               *reinterpret_cast<uint32_t*>(&p1));
        *(uint2*)(outh + (size_t)(hw0+hwl)*CC + cp4*4) = val;
    }
}

// ---------------- fp16 packed MLP (8 -> 16 -> 8 -> 1) ----------------
__device__ __forceinline__ __half2 u2h(uint32_t u) { return *reinterpret_cast<__half2*>(&u); }

__device__ __forceinline__ float mlp8h(const uint32_t* __restrict__ swh, const float in8[8]) {
    __half2 ind[8];
    #pragma unroll
    for (int g = 0; g < 8; g++) ind[g] = __float2half2_rn(in8[g]);
    const uint4* W0 = (const uint4*)swh;
    const uint4* W1 = (const uint4*)(swh + 80);
    const __half2 zero = __float2half2_rn(0.f);
    __half2 h1[8];
    #pragma unroll
    for (int jp = 0; jp < 8; jp++) {
        uint4 wa = W0[jp*2], wb = W0[jp*2+1];
        __half2 acc = __hmul2(u2h(wa.x), ind[0]);
        acc = __hfma2(u2h(wa.y), ind[1], acc);
        acc = __hfma2(u2h(wa.z), ind[2], acc);
        acc = __hfma2(u2h(wa.w), ind[3], acc);
        acc = __hfma2(u2h(wb.x), ind[4], acc);
        acc = __hfma2(u2h(wb.y), ind[5], acc);
        acc = __hfma2(u2h(wb.z), ind[6], acc);
        acc = __hfma2(u2h(wb.w), ind[7], acc);
        acc = __hfma2(acc, u2h(swh[64 + jp]), u2h(swh[72 + jp]));
        h1[jp] = __hmax2(acc, zero);
    }
    __half2 hd[16];
    #pragma unroll
    for (int jp = 0; jp < 8; jp++) {
        hd[2*jp]   = __low2half2(h1[jp]);
        hd[2*jp+1] = __high2half2(h1[jp]);
    }
    __half2 oacc = zero;
    #pragma unroll
    for (int kp = 0; kp < 4; kp++) {
        uint4 w0v = W1[kp*4], w1v = W1[kp*4+1], w2v = W1[kp*4+2], w3v = W1[kp*4+3];
        __half2 acc = __hmul2(u2h(w0v.x), hd[0]);
        acc = __hfma2(u2h(w0v.y), hd[1], acc);
        acc = __hfma2(u2h(w0v.z), hd[2], acc);
        acc = __hfma2(u2h(w0v.w), hd[3], acc);
        acc = __hfma2(u2h(w1v.x), hd[4], acc);
        acc = __hfma2(u2h(w1v.y), hd[5], acc);
        acc = __hfma2(u2h(w1v.z), hd[6], acc);
        acc = __hfma2(u2h(w1v.w), hd[7], acc);
        acc = __hfma2(u2h(w2v.x), hd[8], acc);
        acc = __hfma2(u2h(w2v.y), hd[9], acc);
        acc = __hfma2(u2h(w2v.z), hd[10], acc);
        acc = __hfma2(u2h(w2v.w), hd[11], acc);
        acc = __hfma2(u2h(w3v.x), hd[12], acc);
        acc = __hfma2(u2h(w3v.y), hd[13], acc);
        acc = __hfma2(u2h(w3v.z), hd[14], acc);
        acc = __hfma2(u2h(w3v.w), hd[15], acc);
        acc = __hfma2(acc, u2h(swh[144 + kp]), u2h(swh[148 + kp]));
        acc = __hmax2(acc, zero);
        oacc = __hfma2(u2h(swh[152 + kp]), acc, oacc);
    }
    float2 of = __half22float2(oacc);
    return of.x + of.y + __uint_as_float(swh[156]);
}

// ---------------- K2: warp + group correlation + pixelwise net + similarity net ----------------
// block = 256 threads = 16 pixels × 16 lanes; lane = (dh, g).
__global__ void __launch_bounds__(KM_THREADS)
k_main(const float* __restrict__ depth_sample,
       const float* __restrict__ pw_w0, const float* __restrict__ pw_g0, const float* __restrict__ pw_b0,
       const float* __restrict__ pw_w1, const float* __restrict__ pw_g1, const float* __restrict__ pw_b1,
       const float* __restrict__ pw_w2, const float* __restrict__ pw_c2b,
       const float* __restrict__ sn_w0, const float* __restrict__ sn_g0, const float* __restrict__ sn_b0,
       const float* __restrict__ sn_w1, const float* __restrict__ sn_g1, const float* __restrict__ sn_b1,
       const float* __restrict__ sn_w2, const float* __restrict__ sn_c2b,
       float* __restrict__ out_vw) {
    __shared__ __align__(16) uint32_t swh[2][160];
    __shared__ __align__(16) uint32_t scoord[KM_PIX][16][6]; // packed coords, stride 6 words
    __shared__ uint32_t simh [KM_PIX][16][5];  // [pix][d][4 half2 + pad]; stride 5

    int tid = threadIdx.x;

    // pack fp16 MLP weights
    for (int i = tid; i < 320; i += KM_THREADS) {
        int net = i / 160, j = i - net*160;
        const float* w0 = net ? sn_w0 : pw_w0;
        const float* g0 = net ? sn_g0 : pw_g0;
        const float* b0 = net ? sn_b0 : pw_b0;
        const float* w1 = net ? sn_w1 : pw_w1;
        const float* g1 = net ? sn_g1 : pw_g1;
        const float* b1 = net ? sn_b1 : pw_b1;
        const float* w2 = net ? sn_w2 : pw_w2;
        const float* cb = net ? sn_c2b : pw_c2b;
        uint32_t val;
        if (j < 64) {
            int jp = j >> 3, g = j & 7;
            __half2 h = __floats2half2_rn(w0[(2*jp)*8 + g], w0[(2*jp+1)*8 + g]);
            val = *reinterpret_cast<uint32_t*>(&h);
        } else if (j < 72) {
            int jp = j - 64;
            __half2 h = __floats2half2_rn(g0[2*jp]*BNS, g0[2*jp+1]*BNS);
            val = *reinterpret_cast<uint32_t*>(&h);
        } else if (j < 80) {
            int jp = j - 72;
            __half2 h = __floats2half2_rn(b0[2*jp], b0[2*jp+1]);
            val = *reinterpret_cast<uint32_t*>(&h);
        } else if (j < 144) {
            int idx = j - 80; int kp = idx >> 4, jj = idx & 15;
            __half2 h = __floats2half2_rn(w1[(2*kp)*16 + jj], w1[(2*kp+1)*16 + jj]);
            val = *reinterpret_cast<uint32_t*>(&h);
        } else if (j < 148) {
            int kp = j - 144;
            __half2 h = __floats2half2_rn(g1[2*kp]*BNS, g1[2*kp+1]*BNS);
            val = *reinterpret_cast<uint32_t*>(&h);
        } else if (j < 152) {
            int kp = j - 148;
            __half2 h = __floats2half2_rn(b1[2*kp], b1[2*kp+1]);
            val = *reinterpret_cast<uint32_t*>(&h);
        } else if (j < 156) {
            int kp = j - 152;
            __half2 h = __floats2half2_rn(w2[2*kp], w2[2*kp+1]);
            val = *reinterpret_cast<uint32_t*>(&h);
        } else {
            val = __float_as_uint(cb[0]);
        }
        swh[net][j] = val;
    }
    __syncthreads();

    int pix  = tid >> 4;         // 0..15 within block (2 pixels per warp)
    int lane = tid & 15;         // 0..15: owned depth
    int dh   = lane >> 3;        // depth-half for Phase B
    int g    = lane & 7;         // group for Phase B
    int p = blockIdx.x * KM_PIX + pix;
    int b  = p / HWP;
    int hw = p - b * HWP;
    int h = hw / WW, w = hw - h * WW;
    float wf = (float)w, hf = (float)h;

    // ref features for group g (8 channels fp16 = one uint4)
    uint4 ru = __ldg((const uint4*)(g_refT + (size_t)p*CC) + g);
    __half2 rh0 = u2h(ru.x), rh1 = u2h(ru.y), rh2 = u2h(ru.z), rh3 = u2h(ru.w);

    // depth owned by this lane
    float myDep = __ldg(depth_sample + (size_t)b*DD*HWP + (size_t)lane*HWP + hw);

    float acc[8];
    #pragma unroll
    for (int k = 0; k < 8; k++) acc[k] = 0.f;
    float wsum = 0.f;

    for (int v = 0; v < VV; v++) {
        const float* M = g_proj + (v*BB + b)*12;
        float rx = M[0]*wf + M[1]*hf + M[2];
        float ry = M[4]*wf + M[5]*hf + M[6];
        float rz = M[8]*wf + M[9]*hf + M[10];
        float t0 = M[3], t1 = M[7], t2 = M[11];
        const __half* srcB = g_srcT + (size_t)(v*BB + b)*HWP*CC;

        // ---- Phase A: coords for owned depth (packed to 4 words) ----
        {
            float px = rx*myDep + t0, py = ry*myDep + t1, pz = rz*myDep + t2;
            if (pz <= 0.001f) { px = (float)WW; py = (float)HH; pz = 1.f; }
            float ix = __fdividef(px, pz);
            float iy = __fdividef(py, pz);
            float x0f = floorf(ix), y0f = floorf(iy);
            float fx = ix - x0f, fy = iy - y0f;
            int x0 = (int)x0f, y0 = (int)y0f;
            int x1 = x0 + 1, y1 = y0 + 1;
            bool vx0 = (x0 >= 0) & (x0 < WW);
            bool vx1 = (x1 >= 0) & (x1 < WW);
            bool vy0 = (y0 >= 0) & (y0 < HH);
            bool vy1 = (y1 >= 0) & (y1 < HH);
            float w00 = (1.f-fx)*(1.f-fy) * (float)(vx0 && vy0);
            float w01 = fx*(1.f-fy)       * (float)(vx1 && vy0);
            float w10 = (1.f-fx)*fy       * (float)(vx0 && vy1);
            float w11 = fx*fy             * (float)(vx1 && vy1);
            int xc0 = min(max(x0, 0), WW-1), xc1 = min(max(x1, 0), WW-1);
            int yc0 = min(max(y0, 0), HH-1), yc1 = min(max(y1, 0), HH-1);
            int r0 = yc0*WW, r1 = yc1*WW;
            uint32_t i00 = (uint32_t)(r0 + xc0), i01 = (uint32_t)(r0 + xc1);
            uint32_t i10 = (uint32_t)(r1 + xc0), i11 = (uint32_t)(r1 + xc1);
            __half2 hw01 = __floats2half2_rn(w00, w01);
            __half2 hw23 = __floats2half2_rn(w10, w11);
            uint32_t* sc = scoord[pix][lane];
            *(uint2*)&sc[0] = make_uint2(i00 | (i01 << 16), i10 | (i11 << 16));
            *(uint2*)&sc[2] = make_uint2(*reinterpret_cast<uint32_t*>(&hw01),
                                         *reinterpret_cast<uint32_t*>(&hw23));
        }
        __syncwarp();

        // ---- Phase B: 8 depths per lane (lane = dh half, group g) ----
        #pragma unroll
        for (int dl = 0; dl < 8; dl++) {
            int d = dh*8 + dl;
            uint2 ia = *(const uint2*)&scoord[pix][d][0];
            uint2 wv = *(const uint2*)&scoord[pix][d][2];
            uint32_t i00 = ia.x & 0xFFFFu, i01 = ia.x >> 16;
            uint32_t i10 = ia.y & 0xFFFFu, i11 = ia.y >> 16;
            __half2 pw01 = u2h(wv.x), pw23 = u2h(wv.y);
            __half2 w00 = __low2half2(pw01),  w01 = __high2half2(pw01);
            __half2 w10 = __low2half2(pw23),  w11 = __high2half2(pw23);
            uint4 u00 = __ldg((const uint4*)(srcB + (size_t)i00*CC) + g);
            uint4 u01 = __ldg((const uint4*)(srcB + (size_t)i01*CC) + g);
            uint4 u10 = __ldg((const uint4*)(srcB + (size_t)i10*CC) + g);
            uint4 u11 = __ldg((const uint4*)(srcB + (size_t)i11*CC) + g);
            __half2 m0 = __hmul2(u2h(u00.x), w00);
            __half2 m1 = __hmul2(u2h(u00.y), w00);
            __half2 m2 = __hmul2(u2h(u00.z), w00);
            __half2 m3 = __hmul2(u2h(u00.w), w00);
            m0 = __hfma2(u2h(u01.x), w01, m0);
            m1 = __hfma2(u2h(u01.y), w01, m1);
            m2 = __hfma2(u2h(u01.z), w01, m2);
            m3 = __hfma2(u2h(u01.w), w01, m3);
            m0 = __hfma2(u2h(u10.x), w10, m0);
            m1 = __hfma2(u2h(u10.y), w10, m1);
            m2 = __hfma2(u2h(u10.z), w10, m2);
            m3 = __hfma2(u2h(u10.w), w10, m3);
            m0 = __hfma2(u2h(u11.x), w11, m0);
            m1 = __hfma2(u2h(u11.y), w11, m1);
            m2 = __hfma2(u2h(u11.z), w11, m2);
            m3 = __hfma2(u2h(u11.w), w11, m3);
            __half2 da = __hmul2(m0, rh0);
            da = __hfma2(m1, rh1, da);
            da = __hfma2(m2, rh2, da);
            da = __hfma2(m3, rh3, da);
            float2 df = __half22float2(da);
            ((__half*)&simh[pix][d][0])[g] = __float2half_rn((df.x + df.y) * 0.125f);
        }
        __syncwarp();

        // ---- pixelwise net: lane owns depth = lane ----
        const uint32_t* sv = simh[pix][lane];
        float in8[8];
        {
            float2 a0 = __half22float2(u2h(sv[0]));
            float2 a1 = __half22float2(u2h(sv[1]));
            float2 a2 = __half22float2(u2h(sv[2]));
            float2 a3 = __half22float2(u2h(sv[3]));
            in8[0]=a0.x; in8[1]=a0.y; in8[2]=a1.x; in8[3]=a1.y;
            in8[4]=a2.x; in8[5]=a2.y; in8[6]=a3.x; in8[7]=a3.y;
        }
        float o = mlp8h(swh[0], in8);
        float vwv = __frcp_rn(1.f + __expf(-o));
        #pragma unroll
        for (int k = 8; k >= 1; k >>= 1)
            vwv = fmaxf(vwv, __shfl_xor_sync(0xffffffffu, vwv, k, 16));
        #pragma unroll
        for (int k = 0; k < 8; k++) acc[k] += in8[k]*vwv;
        wsum += vwv;
        if (lane == 0) out_vw[((size_t)b*VV + v)*HWP + hw] = vwv;
        __syncwarp();
    }

    float rws = 1.f / wsum;
    float in8[8];
    #pragma unroll
    for (int k = 0; k < 8; k++) in8[k] = acc[k]*rws;
    float sval = mlp8h(swh[1], in8);
    g_s[(size_t)p*DD + lane] = sval;
}

// ---------------- K3: grid-sample + NN aggregation + softmax + depth ----------------
// 4 threads per pixel; thread q owns depths [4q, 4q+4)
__global__ void __launch_bounds__(128)
k_final(const float* __restrict__ grid, const float* __restrict__ weight,
        const float* __restrict__ depth_sample, const int* __restrict__ is_inverse,
        float* __restrict__ out_depth, float* __restrict__ out_score) {
    int t = blockIdx.x * blockDim.x + threadIdx.x;
    int p = t >> 2;
    int q = t & 3;
    if (p >= BB*HWP) return;
    int b  = p / HWP;
    int hw = p - b * HWP;
    int h = hw / WW, w = hw - h * WW;

    float agg[4] = {0.f, 0.f, 0.f, 0.f};

    const float* wbase = weight + ((size_t)b*DD*NV)*HWP + hw + (size_t)(q*4)*NV*HWP;
    #pragma unroll
    for (int n = 0; n < NV; n++) {
        const float* gp = grid + (((size_t)b*NV*HH + n*HH + h)*WW + w)*2;
        float gx = __ldg(gp), gy = __ldg(gp + 1);
        float ix = ((gx + 1.f)*WW - 1.f) * 0.5f;
        float iy = ((gy + 1.f)*HH - 1.f) * 0.5f;
        float x0f = floorf(ix), y0f = floorf(iy);
        float fx = ix - x0f, fy = iy - y0f;
        int x0 = (int)x0f, y0 = (int)y0f;
        int xc0 = min(max(x0, 0), WW-1), xc1 = min(max(x0+1, 0), WW-1);
        int yc0 = min(max(y0, 0), HH-1), yc1 = min(max(y0+1, 0), HH-1);
        float w00 = (1.f-fx)*(1.f-fy), w01 = fx*(1.f-fy);
        float w10 = (1.f-fx)*fy,       w11 = fx*fy;
        float4 a00 = __ldg((const float4*)(g_s + ((size_t)b*HWP + yc0*WW + xc0)*DD) + q);
        float4 a01 = __ldg((const float4*)(g_s + ((size_t)b*HWP + yc0*WW + xc1)*DD) + q);
        float4 a10 = __ldg((const float4*)(g_s + ((size_t)b*HWP + yc1*WW + xc0)*DD) + q);
        float4 a11 = __ldg((const float4*)(g_s + ((size_t)b*HWP + yc1*WW + xc1)*DD) + q);
        float bx = w00*a00.x + w01*a01.x + w10*a10.x + w11*a11.x;
        float by = w00*a00.y + w01*a01.y + w10*a10.y + w11*a11.y;
        float bz = w00*a00.z + w01*a01.z + w10*a10.z + w11*a11.z;
        float bw = w00*a00.w + w01*a01.w + w10*a10.w + w11*a11.w;
        const float* wb = wbase + (size_t)n*HWP;
        agg[0] += __ldg(wb)                      * bx;
        agg[1] += __ldg(wb + (size_t)1*NV*HWP)   * by;
        agg[2] += __ldg(wb + (size_t)2*NV*HWP)   * bz;
        agg[3] += __ldg(wb + (size_t)3*NV*HWP)   * bw;
    }

    float m = fmaxf(fmaxf(agg[0], agg[1]), fmaxf(agg[2], agg[3]));
    m = fmaxf(m, __shfl_xor_sync(0xffffffffu, m, 1, 4));
    m = fmaxf(m, __shfl_xor_sync(0xffffffffu, m, 2, 4));
    float e[4]; float sum = 0.f;
    #pragma unroll
    for (int j = 0; j < 4; j++) { e[j] = __expf(agg[j] - m); sum += e[j]; }
    sum += __shfl_xor_sync(0xffffffffu, sum, 1, 4);
    sum += __shfl_xor_sync(0xffffffffu, sum, 2, 4);
    float rs = 1.f / sum;

    const float* dsB = depth_sample + (size_t)b*DD*HWP + hw;
    float dep = 0.f;
    int inv = *is_inverse;
    #pragma unroll
    for (int j = 0; j < 4; j++) {
        float sc = e[j] * rs;
        int d = q*4 + j;
        out_score[((size_t)b*DD + d)*HWP + hw] = sc;
        if (inv) dep += (float)d * sc;
        else     dep += __ldg(dsB + (size_t)d*HWP) * sc;
    }
    dep += __shfl_xor_sync(0xffffffffu, dep, 1, 4);
    dep += __shfl_xor_sync(0xffffffffu, dep, 2, 4);
    if (q == 0) {
        if (inv) {
            float invmin = 1.f / __ldg(dsB + (size_t)(DD-1)*HWP);
            float invmax = 1.f / __ldg(dsB);
            dep = 1.f / (invmax + dep * (1.f/(float)(DD-1)) * (invmin - invmax));
        }
        out_depth[p] = dep;
    }
}

// ---------------- launch ----------------
extern "C" void kernel_launch(void* const* d_in, const int* in_sizes, int n_in,
                              void* d_out, int out_size) {
    const float* ref_feature  = (const float*)d_in[0];
    const float* src_features = (const float*)d_in[1];
    const float* ref_proj     = (const float*)d_in[2];
    const float* src_projs    = (const float*)d_in[3];
    const float* depth_sample = (const float*)d_in[4];
    const float* grid         = (const float*)d_in[5];
    const float* weight       = (const float*)d_in[6];
    const float* pw_w0  = (const float*)d_in[7];
    const float* pw_g0  = (const float*)d_in[8];
    const float* pw_b0  = (const float*)d_in[9];
    const float* pw_w1  = (const float*)d_in[10];
    const float* pw_g1  = (const float*)d_in[11];
    const float* pw_b1  = (const float*)d_in[12];
    const float* pw_w2  = (const float*)d_in[13];
    const float* pw_c2b = (const float*)d_in[14];
    const float* sn_w0  = (const float*)d_in[15];
    const float* sn_g0  = (const float*)d_in[16];
    const float* sn_b0  = (const float*)d_in[17];
    const float* sn_w1  = (const float*)d_in[18];
    const float* sn_g1  = (const float*)d_in[19];
    const float* sn_b1  = (const float*)d_in[20];
    const float* sn_w2  = (const float*)d_in[21];
    const float* sn_c2b = (const float*)d_in[22];
    const int*   is_inv = (const int*)d_in[23];

    float* out       = (float*)d_out;
    float* out_depth = out;
    float* out_score = out + (size_t)BB*HWP;
    float* out_vw    = out + (size_t)BB*HWP + (size_t)BB*DD*HWP;

    k_transpose<<<dim3(HWP/64, VV*BB + BB + 1), 256>>>(ref_feature, src_features,
                                                       ref_proj, src_projs);
    k_main<<<BB*HWP/KM_PIX, KM_THREADS>>>(depth_sample,
                              pw_w0, pw_g0, pw_b0, pw_w1, pw_g1, pw_b1, pw_w2, pw_c2b,
                              sn_w0, sn_g0, sn_b0, sn_w1, sn_g1, sn_b1, sn_w2, sn_c2b,
                              out_vw);
    k_final<<<(BB*HWP*4 + 127)/128, 128>>>(grid, weight, depth_sample, is_inv,
                                           out_depth, out_score);
}

// round 14
// speedup vs baseline: 1.0801x; 1.0501x over previous
#include <cuda_runtime.h>
#include <cuda_fp16.h>
#include <math.h>
#include <stdint.h>

#define BB 2
#define CC 64
#define HH 128
#define WW 160
#define DD 16
#define VV 4
#define NV 9
#define HWP (HH*WW)

#define KM_PIX 16                 // pixels per k_main block
#define KM_THREADS (KM_PIX*16)    // 256

// ---------------- scratch (static device memory; no allocation) ----------------
__device__ __align__(16) __half g_srcT[(size_t)VV*BB*HWP*CC]; // fp16 [v*B+b][hw][c]
__device__ __align__(16) __half g_refT[(size_t)BB*HWP*CC];    // fp16 [b][hw][c]
__device__ float g_proj[VV*BB*12];
__device__ __align__(16) float g_s[(size_t)BB*HWP*DD];        // s channels-last [b][hw][d]

#define BNS 0.9999950000374997f

// ---------------- K0: transpose [C,HW] -> [HW,C] (fp32 staging, vectorized) + fused proj ----------------
__global__ void k_transpose(const float* __restrict__ ref, const float* __restrict__ src,
                            const float* __restrict__ ref_proj, const float* __restrict__ src_projs) {
    int img = blockIdx.y;          // 0..7 = src v*B+b, 8..9 = ref b, 10 = proj
    if (img == VV*BB + BB) {
        if (blockIdx.x != 0) return;
        int t = threadIdx.x;
        if (t >= VV*BB) return;
        int v = t / BB, b = t % BB;
        float a[4][4], inv[4][4];
        #pragma unroll
        for (int i = 0; i < 4; i++)
            #pragma unroll
            for (int j = 0; j < 4; j++) {
                a[i][j] = ref_proj[b*16 + i*4 + j];
                inv[i][j] = (i == j) ? 1.f : 0.f;
            }
        for (int col = 0; col < 4; col++) {
            int piv = col; float best = fabsf(a[col][col]);
            for (int r = col+1; r < 4; r++) { float av = fabsf(a[r][col]); if (av > best) { best = av; piv = r; } }
            if (piv != col) {
                for (int j = 0; j < 4; j++) {
                    float tm = a[col][j]; a[col][j] = a[piv][j]; a[piv][j] = tm;
                    tm = inv[col][j]; inv[col][j] = inv[piv][j]; inv[piv][j] = tm;
                }
            }
            float dsc = 1.f / a[col][col];
            for (int j = 0; j < 4; j++) { a[col][j] *= dsc; inv[col][j] *= dsc; }
            for (int r = 0; r < 4; r++) {
                if (r == col) continue;
                float f = a[r][col];
                for (int j = 0; j < 4; j++) { a[r][j] -= f*a[col][j]; inv[r][j] -= f*inv[col][j]; }
            }
        }
        const float* s = src_projs + (size_t)(v*BB + b)*16;
        float* o = g_proj + (v*BB + b)*12;
        for (int i = 0; i < 3; i++)
            for (int j = 0; j < 4; j++) {
                float acc = 0.f;
                for (int k = 0; k < 4; k++) acc += s[i*4 + k] * inv[k][j];
                o[i*4 + j] = acc;
            }
        return;
    }
    __shared__ float tile[64][65];
    int hw0 = blockIdx.x * 64;
    int tid = threadIdx.x;
    const float* in = (img < VV*BB) ? (src + (size_t)img*CC*HWP)
                                    : (ref + (size_t)(img - VV*BB)*CC*HWP);
    #pragma unroll
    for (int k = tid; k < 1024; k += 256) {
        int c   = k >> 4;
        int hw4 = k & 15;
        float4 v = *(const float4*)(in + (size_t)c*HWP + hw0 + hw4*4);
        tile[hw4*4+0][c] = v.x;
        tile[hw4*4+1][c] = v.y;
        tile[hw4*4+2][c] = v.z;
        tile[hw4*4+3][c] = v.w;
    }
    __syncthreads();
    __half* outh = (img < VV*BB)
        ? (g_srcT + (size_t)img*HWP*CC)
        : (g_refT + (size_t)(img - VV*BB)*HWP*CC);
    #pragma unroll
    for (int k = tid; k < 1024; k += 256) {
        int hwl = k >> 4;
        int cp4 = k & 15;
        const float* tr = &tile[hwl][cp4*4];
        __half2 p0 = __floats2half2_rn(tr[0], tr[1]);
        __half2 p1 = __floats2half2_rn(tr[2], tr[3]);
        uint2 val = make_uint2(*reinterpret_cast<uint32_t*>(&p0),
                               *reinterpret_cast<uint32_t*>(&p1));
        *(uint2*)(outh + (size_t)(hw0+hwl)*CC + cp4*4) = val;
    }
}

// ---------------- tensor-core helpers ----------------
__device__ __forceinline__ __half2 u2h(uint32_t u) { return *reinterpret_cast<__half2*>(&u); }
__device__ __forceinline__ uint32_t h2u(__half2 h) { return *reinterpret_cast<uint32_t*>(&h); }

__device__ __forceinline__ void ldmatrix_x4(uint32_t& r0, uint32_t& r1, uint32_t& r2, uint32_t& r3,
                                            uint32_t addr) {
    asm volatile("ldmatrix.sync.aligned.m8n8.x4.shared.b16 {%0,%1,%2,%3}, [%4];"
                 : "=r"(r0), "=r"(r1), "=r"(r2), "=r"(r3) : "r"(addr));
}

__device__ __forceinline__ void mma_16n8k8(float d[4], uint32_t a0, uint32_t a1, uint32_t b0) {
    float z = 0.f;
    asm volatile("mma.sync.aligned.m16n8k8.row.col.f32.f16.f16.f32 "
                 "{%0,%1,%2,%3},{%4,%5},{%6},{%7,%8,%9,%10};"
                 : "=f"(d[0]), "=f"(d[1]), "=f"(d[2]), "=f"(d[3])
                 : "r"(a0), "r"(a1), "r"(b0), "f"(z), "f"(z), "f"(z), "f"(z));
}

__device__ __forceinline__ void mma_16n8k16(float d[4], uint32_t a0, uint32_t a1, uint32_t a2, uint32_t a3,
                                            uint32_t b0, uint32_t b1) {
    float z = 0.f;
    asm volatile("mma.sync.aligned.m16n8k16.row.col.f32.f16.f16.f32 "
                 "{%0,%1,%2,%3},{%4,%5,%6,%7},{%8,%9},{%10,%11,%12,%13};"
                 : "=f"(d[0]), "=f"(d[1]), "=f"(d[2]), "=f"(d[3])
                 : "r"(a0), "r"(a1), "r"(a2), "r"(a3), "r"(b0), "r"(b1),
                   "f"(z), "f"(z), "f"(z), "f"(z));
}

// warp-cooperative MLP: 32 samples (rows) x 8 inputs -> per-row scalar output.
// P: f32 params [w0(128), gs0@128(16), b0@144(16), w1@160(128), gs1@288(8), b1@296(8), w2@304(8), c2b@312]
// o[m][0] = output row q of m-tile m, o[m][1] = row q+8.
__device__ __forceinline__ void mlp_tc(const float* __restrict__ P,
                                       uint32_t bL1n0, uint32_t bL1n1,
                                       uint32_t bL2k0, uint32_t bL2k1,
                                       uint32_t lmaddr, int c2v, float o[2][2]) {
    uint32_t A0, A1, A2, A3;
    ldmatrix_x4(A0, A1, A2, A3, lmaddr);
    float gj0a = P[128 + c2v],     gj1a = P[128 + c2v + 1];
    float gj0b = P[128 + c2v + 8], gj1b = P[128 + c2v + 9];
    float bj0a = P[144 + c2v],     bj1a = P[144 + c2v + 1];
    float bj0b = P[144 + c2v + 8], bj1b = P[144 + c2v + 9];
    float gn0 = P[288 + c2v], gn1 = P[288 + c2v + 1];
    float bn0 = P[296 + c2v], bn1 = P[296 + c2v + 1];
    float w2a = P[304 + c2v], w2b = P[304 + c2v + 1];
    float c2b = P[312];
    #pragma unroll
    for (int m = 0; m < 2; m++) {
        uint32_t a0 = m ? A2 : A0, a1 = m ? A3 : A1;
        float d0[4], d1[4];
        mma_16n8k8(d0, a0, a1, bL1n0);
        mma_16n8k8(d1, a0, a1, bL1n1);
        float h00 = fmaxf(0.f, d0[0]*gj0a + bj0a), h01 = fmaxf(0.f, d0[1]*gj1a + bj1a);
        float h02 = fmaxf(0.f, d0[2]*gj0a + bj0a), h03 = fmaxf(0.f, d0[3]*gj1a + bj1a);
        float h10 = fmaxf(0.f, d1[0]*gj0b + bj0b), h11 = fmaxf(0.f, d1[1]*gj1b + bj1b);
        float h12 = fmaxf(0.f, d1[2]*gj0b + bj0b), h13 = fmaxf(0.f, d1[3]*gj1b + bj1b);
        uint32_t e0 = h2u(__floats2half2_rn(h00, h01));
        uint32_t e1 = h2u(__floats2half2_rn(h02, h03));
        uint32_t e2 = h2u(__floats2half2_rn(h10, h11));
        uint32_t e3 = h2u(__floats2half2_rn(h12, h13));
        float d2[4];
        mma_16n8k16(d2, e0, e1, e2, e3, bL2k0, bL2k1);
        float f0 = fmaxf(0.f, d2[0]*gn0 + bn0), f1 = fmaxf(0.f, d2[1]*gn1 + bn1);
        float f2 = fmaxf(0.f, d2[2]*gn0 + bn0), f3 = fmaxf(0.f, d2[3]*gn1 + bn1);
        float p0 = w2a*f0 + w2b*f1;
        float p1 = w2a*f2 + w2b*f3;
        p0 += __shfl_xor_sync(0xffffffffu, p0, 1);
        p0 += __shfl_xor_sync(0xffffffffu, p0, 2);
        p1 += __shfl_xor_sync(0xffffffffu, p1, 1);
        p1 += __shfl_xor_sync(0xffffffffu, p1, 2);
        o[m][0] = p0 + c2b;
        o[m][1] = p1 + c2b;
    }
}

// ---------------- K2: warp + group correlation + tensor-core MLPs ----------------
// block = 256 threads = 16 pixels × 16 lanes; warp covers 2 pixels (32 samples).
#define SIMS 24   // simh row stride in halves (48B, 16B-aligned, conflict-free ldmatrix)
__global__ void __launch_bounds__(KM_THREADS)
k_main(const float* __restrict__ depth_sample,
       const float* __restrict__ pw_w0, const float* __restrict__ pw_g0, const float* __restrict__ pw_b0,
       const float* __restrict__ pw_w1, const float* __restrict__ pw_g1, const float* __restrict__ pw_b1,
       const float* __restrict__ pw_w2, const float* __restrict__ pw_c2b,
       const float* __restrict__ sn_w0, const float* __restrict__ sn_g0, const float* __restrict__ sn_b0,
       const float* __restrict__ sn_w1, const float* __restrict__ sn_g1, const float* __restrict__ sn_b1,
       const float* __restrict__ sn_w2, const float* __restrict__ sn_c2b,
       float* __restrict__ out_vw) {
    __shared__ float sfp[2][320];
    __shared__ __align__(16) uint32_t scoord[KM_PIX][16][6];   // packed coords, stride 6 words
    __shared__ __align__(16) __half simh[KM_PIX*16*SIMS];      // rows: pix*16+d, 8 valid halves

    int tid = threadIdx.x;

    // plain f32 param staging
    for (int i = tid; i < 640; i += KM_THREADS) {
        int net = i / 320, j = i - net*320;
        const float* w0 = net ? sn_w0 : pw_w0;
        const float* g0 = net ? sn_g0 : pw_g0;
        const float* b0 = net ? sn_b0 : pw_b0;
        const float* w1 = net ? sn_w1 : pw_w1;
        const float* g1 = net ? sn_g1 : pw_g1;
        const float* b1 = net ? sn_b1 : pw_b1;
        const float* w2 = net ? sn_w2 : pw_w2;
        const float* cb = net ? sn_c2b : pw_c2b;
        float val;
        if      (j < 128) val = w0[j];
        else if (j < 144) val = g0[j-128] * BNS;
        else if (j < 160) val = b0[j-144];
        else if (j < 288) val = w1[j-160];
        else if (j < 296) val = g1[j-288] * BNS;
        else if (j < 304) val = b1[j-296];
        else if (j < 312) val = w2[j-304];
        else if (j == 312) val = cb[0];
        else val = 0.f;
        sfp[net][j] = val;
    }
    __syncthreads();

    int l   = tid & 31;          // lane in warp
    int q   = l >> 2;
    int c2v = (l & 3) * 2;
    int warpid = tid >> 5;

    // B fragments (per lane, both nets)
    uint32_t bw0[2][2], bw1[2][2];
    #pragma unroll
    for (int t = 0; t < 2; t++) {
        const float* P = sfp[t];
        bw0[t][0] = h2u(__floats2half2_rn(P[q*8 + c2v],        P[q*8 + c2v + 1]));
        bw0[t][1] = h2u(__floats2half2_rn(P[(q+8)*8 + c2v],    P[(q+8)*8 + c2v + 1]));
        bw1[t][0] = h2u(__floats2half2_rn(P[160 + q*16 + c2v],     P[160 + q*16 + c2v + 1]));
        bw1[t][1] = h2u(__floats2half2_rn(P[160 + q*16 + 8 + c2v], P[160 + q*16 + 9 + c2v]));
    }

    int pix  = tid >> 4;         // 0..15 in block
    int lane = tid & 15;         // owned depth
    int dh   = lane >> 3;
    int g    = lane & 7;
    int p = blockIdx.x * KM_PIX + pix;
    int b  = p / HWP;
    int hw = p - b * HWP;
    int h = hw / WW, w = hw - h * WW;
    float wf = (float)w, hf = (float)h;

    // row address for this lane's sample row (= ldmatrix row and own-depth row)
    uint32_t sbase = (uint32_t)__cvta_generic_to_shared(simh);
    uint32_t lmaddr = sbase + (uint32_t)(warpid*32 + l) * (SIMS*2);
    __half* myrow = simh + (warpid*32 + l) * SIMS;

    // ref features for group g
    uint4 ru = __ldg((const uint4*)(g_refT + (size_t)p*CC) + g);
    __half2 rh0 = u2h(ru.x), rh1 = u2h(ru.y), rh2 = u2h(ru.z), rh3 = u2h(ru.w);

    float myDep = __ldg(depth_sample + (size_t)b*DD*HWP + (size_t)lane*HWP + hw);

    float acc[8];
    #pragma unroll
    for (int k = 0; k < 8; k++) acc[k] = 0.f;
    float wsum = 0.f;

    for (int v = 0; v < VV; v++) {
        const float* M = g_proj + (v*BB + b)*12;
        float rx = M[0]*wf + M[1]*hf + M[2];
        float ry = M[4]*wf + M[5]*hf + M[6];
        float rz = M[8]*wf + M[9]*hf + M[10];
        float t0 = M[3], t1 = M[7], t2 = M[11];
        const __half* srcB = g_srcT + (size_t)(v*BB + b)*HWP*CC;

        // ---- Phase A: coords for owned depth ----
        {
            float px = rx*myDep + t0, py = ry*myDep + t1, pz = rz*myDep + t2;
            if (pz <= 0.001f) { px = (float)WW; py = (float)HH; pz = 1.f; }
            float ix = __fdividef(px, pz);
            float iy = __fdividef(py, pz);
            float x0f = floorf(ix), y0f = floorf(iy);
            float fx = ix - x0f, fy = iy - y0f;
            int x0 = (int)x0f, y0 = (int)y0f;
            int x1 = x0 + 1, y1 = y0 + 1;
            bool vx0 = (x0 >= 0) & (x0 < WW);
            bool vx1 = (x1 >= 0) & (x1 < WW);
            bool vy0 = (y0 >= 0) & (y0 < HH);
            bool vy1 = (y1 >= 0) & (y1 < HH);
            float w00 = (1.f-fx)*(1.f-fy) * (float)(vx0 && vy0);
            float w01 = fx*(1.f-fy)       * (float)(vx1 && vy0);
            float w10 = (1.f-fx)*fy       * (float)(vx0 && vy1);
            float w11 = fx*fy             * (float)(vx1 && vy1);
            int xc0 = min(max(x0, 0), WW-1), xc1 = min(max(x1, 0), WW-1);
            int yc0 = min(max(y0, 0), HH-1), yc1 = min(max(y1, 0), HH-1);
            int r0 = yc0*WW, r1 = yc1*WW;
            uint32_t i00 = (uint32_t)(r0 + xc0), i01 = (uint32_t)(r0 + xc1);
            uint32_t i10 = (uint32_t)(r1 + xc0), i11 = (uint32_t)(r1 + xc1);
            __half2 hw01 = __floats2half2_rn(w00, w01);
            __half2 hw23 = __floats2half2_rn(w10, w11);
            uint32_t* sc = scoord[pix][lane];
            *(uint2*)&sc[0] = make_uint2(i00 | (i01 << 16), i10 | (i11 << 16));
            *(uint2*)&sc[2] = make_uint2(h2u(hw01), h2u(hw23));
        }
        __syncwarp();

        // ---- Phase B: 8 depths per lane ----
        #pragma unroll
        for (int dl = 0; dl < 8; dl++) {
            int d = dh*8 + dl;
            uint2 ia = *(const uint2*)&scoord[pix][d][0];
            uint2 wv = *(const uint2*)&scoord[pix][d][2];
            uint32_t i00 = ia.x & 0xFFFFu, i01 = ia.x >> 16;
            uint32_t i10 = ia.y & 0xFFFFu, i11 = ia.y >> 16;
            __half2 pw01 = u2h(wv.x), pw23 = u2h(wv.y);
            __half2 w00 = __low2half2(pw01),  w01 = __high2half2(pw01);
            __half2 w10 = __low2half2(pw23),  w11 = __high2half2(pw23);
            uint4 u00 = __ldg((const uint4*)(srcB + (size_t)i00*CC) + g);
            uint4 u01 = __ldg((const uint4*)(srcB + (size_t)i01*CC) + g);
            uint4 u10 = __ldg((const uint4*)(srcB + (size_t)i10*CC) + g);
            uint4 u11 = __ldg((const uint4*)(srcB + (size_t)i11*CC) + g);
            __half2 m0 = __hmul2(u2h(u00.x), w00);
            __half2 m1 = __hmul2(u2h(u00.y), w00);
            __half2 m2 = __hmul2(u2h(u00.z), w00);
            __half2 m3 = __hmul2(u2h(u00.w), w00);
            m0 = __hfma2(u2h(u01.x), w01, m0);
            m1 = __hfma2(u2h(u01.y), w01, m1);
            m2 = __hfma2(u2h(u01.z), w01, m2);
            m3 = __hfma2(u2h(u01.w), w01, m3);
            m0 = __hfma2(u2h(u10.x), w10, m0);
            m1 = __hfma2(u2h(u10.y), w10, m1);
            m2 = __hfma2(u2h(u10.z), w10, m2);
            m3 = __hfma2(u2h(u10.w), w10, m3);
            m0 = __hfma2(u2h(u11.x), w11, m0);
            m1 = __hfma2(u2h(u11.y), w11, m1);
            m2 = __hfma2(u2h(u11.z), w11, m2);
            m3 = __hfma2(u2h(u11.w), w11, m3);
            __half2 da = __hmul2(m0, rh0);
            da = __hfma2(m1, rh1, da);
            da = __hfma2(m2, rh2, da);
            da = __hfma2(m3, rh3, da);
            float2 df = __half22float2(da);
            simh[(pix*16 + d)*SIMS + g] = __float2half_rn((df.x + df.y) * 0.125f);
        }
        __syncwarp();

        // ---- pixelwise net (tensor cores, whole warp = 32 samples) ----
        float o[2][2];
        mlp_tc(sfp[0], bw0[0][0], bw0[0][1], bw1[0][0], bw1[0][1], lmaddr, c2v, o);

        // per-pixel max over depths, sigmoid
        float m0 = fmaxf(o[0][0], o[0][1]);
        float m1 = fmaxf(o[1][0], o[1][1]);
        m0 = fmaxf(m0, __shfl_xor_sync(0xffffffffu, m0, 4));
        m1 = fmaxf(m1, __shfl_xor_sync(0xffffffffu, m1, 4));
        m0 = fmaxf(m0, __shfl_xor_sync(0xffffffffu, m0, 8));
        m1 = fmaxf(m1, __shfl_xor_sync(0xffffffffu, m1, 8));
        m0 = fmaxf(m0, __shfl_xor_sync(0xffffffffu, m0, 16));
        m1 = fmaxf(m1, __shfl_xor_sync(0xffffffffu, m1, 16));
        float omax = (l & 16) ? m1 : m0;
        float vwv = __frcp_rn(1.f + __expf(-omax));

        if (lane == 0) out_vw[((size_t)b*VV + v)*HWP + hw] = vwv;

        // accumulate own-depth sims
        uint4 sv = *(const uint4*)myrow;
        float2 a0 = __half22float2(u2h(sv.x));
        float2 a1 = __half22float2(u2h(sv.y));
        float2 a2 = __half22float2(u2h(sv.z));
        float2 a3 = __half22float2(u2h(sv.w));
        acc[0] += a0.x*vwv; acc[1] += a0.y*vwv; acc[2] += a1.x*vwv; acc[3] += a1.y*vwv;
        acc[4] += a2.x*vwv; acc[5] += a2.y*vwv; acc[6] += a3.x*vwv; acc[7] += a3.y*vwv;
        wsum += vwv;
        __syncwarp();
    }

    // ---- similarity net ----
    float rws = 1.f / wsum;
    {
        __half2 s0 = __floats2half2_rn(acc[0]*rws, acc[1]*rws);
        __half2 s1 = __floats2half2_rn(acc[2]*rws, acc[3]*rws);
        __half2 s2 = __floats2half2_rn(acc[4]*rws, acc[5]*rws);
        __half2 s3 = __floats2half2_rn(acc[6]*rws, acc[7]*rws);
        *(uint4*)myrow = make_uint4(h2u(s0), h2u(s1), h2u(s2), h2u(s3));
    }
    __syncwarp();
    float o2[2][2];
    mlp_tc(sfp[1], bw0[1][0], bw0[1][1], bw1[1][0], bw1[1][1], lmaddr, c2v, o2);

    if ((l & 3) == 0) {
        int pbase = blockIdx.x * KM_PIX + 2*warpid;
        g_s[(size_t)pbase*DD + q]          = o2[0][0];
        g_s[(size_t)pbase*DD + q + 8]      = o2[0][1];
        g_s[(size_t)(pbase+1)*DD + q]      = o2[1][0];
        g_s[(size_t)(pbase+1)*DD + q + 8]  = o2[1][1];
    }
}

// ---------------- K3: grid-sample + NN aggregation + softmax + depth ----------------
__global__ void __launch_bounds__(128)
k_final(const float* __restrict__ grid, const float* __restrict__ weight,
        const float* __restrict__ depth_sample, const int* __restrict__ is_inverse,
        float* __restrict__ out_depth, float* __restrict__ out_score) {
    int t = blockIdx.x * blockDim.x + threadIdx.x;
    int p = t >> 2;
    int q = t & 3;
    if (p >= BB*HWP) return;
    int b  = p / HWP;
    int hw = p - b * HWP;
    int h = hw / WW, w = hw - h * WW;

    float agg[4] = {0.f, 0.f, 0.f, 0.f};

    const float* wbase = weight + ((size_t)b*DD*NV)*HWP + hw + (size_t)(q*4)*NV*HWP;
    #pragma unroll
    for (int n = 0; n < NV; n++) {
        const float* gp = grid + (((size_t)b*NV*HH + n*HH + h)*WW + w)*2;
        float gx = __ldg(gp), gy = __ldg(gp + 1);
        float ix = ((gx + 1.f)*WW - 1.f) * 0.5f;
        float iy = ((gy + 1.f)*HH - 1.f) * 0.5f;
        float x0f = floorf(ix), y0f = floorf(iy);
        float fx = ix - x0f, fy = iy - y0f;
        int x0 = (int)x0f, y0 = (int)y0f;
        int xc0 = min(max(x0, 0), WW-1), xc1 = min(max(x0+1, 0), WW-1);
        int yc0 = min(max(y0, 0), HH-1), yc1 = min(max(y0+1, 0), HH-1);
        float w00 = (1.f-fx)*(1.f-fy), w01 = fx*(1.f-fy);
        float w10 = (1.f-fx)*fy,       w11 = fx*fy;
        float4 a00 = __ldg((const float4*)(g_s + ((size_t)b*HWP + yc0*WW + xc0)*DD) + q);
        float4 a01 = __ldg((const float4*)(g_s + ((size_t)b*HWP + yc0*WW + xc1)*DD) + q);
        float4 a10 = __ldg((const float4*)(g_s + ((size_t)b*HWP + yc1*WW + xc0)*DD) + q);
        float4 a11 = __ldg((const float4*)(g_s + ((size_t)b*HWP + yc1*WW + xc1)*DD) + q);
        float bx = w00*a00.x + w01*a01.x + w10*a10.x + w11*a11.x;
        float by = w00*a00.y + w01*a01.y + w10*a10.y + w11*a11.y;
        float bz = w00*a00.z + w01*a01.z + w10*a10.z + w11*a11.z;
        float bw = w00*a00.w + w01*a01.w + w10*a10.w + w11*a11.w;
        const float* wb = wbase + (size_t)n*HWP;
        agg[0] += __ldg(wb)                      * bx;
        agg[1] += __ldg(wb + (size_t)1*NV*HWP)   * by;
        agg[2] += __ldg(wb + (size_t)2*NV*HWP)   * bz;
        agg[3] += __ldg(wb + (size_t)3*NV*HWP)   * bw;
    }

    float m = fmaxf(fmaxf(agg[0], agg[1]), fmaxf(agg[2], agg[3]));
    m = fmaxf(m, __shfl_xor_sync(0xffffffffu, m, 1, 4));
    m = fmaxf(m, __shfl_xor_sync(0xffffffffu, m, 2, 4));
    float e[4]; float sum = 0.f;
    #pragma unroll
    for (int j = 0; j < 4; j++) { e[j] = __expf(agg[j] - m); sum += e[j]; }
    sum += __shfl_xor_sync(0xffffffffu, sum, 1, 4);
    sum += __shfl_xor_sync(0xffffffffu, sum, 2, 4);
    float rs = 1.f / sum;

    const float* dsB = depth_sample + (size_t)b*DD*HWP + hw;
    float dep = 0.f;
    int inv = *is_inverse;
    #pragma unroll
    for (int j = 0; j < 4; j++) {
        float sc = e[j] * rs;
        int d = q*4 + j;
        out_score[((size_t)b*DD + d)*HWP + hw] = sc;
        if (inv) dep += (float)d * sc;
        else     dep += __ldg(dsB + (size_t)d*HWP) * sc;
    }
    dep += __shfl_xor_sync(0xffffffffu, dep, 1, 4);
    dep += __shfl_xor_sync(0xffffffffu, dep, 2, 4);
    if (q == 0) {
        if (inv) {
            float invmin = 1.f / __ldg(dsB + (size_t)(DD-1)*HWP);
            float invmax = 1.f / __ldg(dsB);
            dep = 1.f / (invmax + dep * (1.f/(float)(DD-1)) * (invmin - invmax));
        }
        out_depth[p] = dep;
    }
}

// ---------------- launch ----------------
extern "C" void kernel_launch(void* const* d_in, const int* in_sizes, int n_in,
                              void* d_out, int out_size) {
    const float* ref_feature  = (const float*)d_in[0];
    const float* src_features = (const float*)d_in[1];
    const float* ref_proj     = (const float*)d_in[2];
    const float* src_projs    = (const float*)d_in[3];
    const float* depth_sample = (const float*)d_in[4];
    const float* grid         = (const float*)d_in[5];
    const float* weight       = (const float*)d_in[6];
    const float* pw_w0  = (const float*)d_in[7];
    const float* pw_g0  = (const float*)d_in[8];
    const float* pw_b0  = (const float*)d_in[9];
    const float* pw_w1  = (const float*)d_in[10];
    const float* pw_g1  = (const float*)d_in[11];
    const float* pw_b1  = (const float*)d_in[12];
    const float* pw_w2  = (const float*)d_in[13];
    const float* pw_c2b = (const float*)d_in[14];
    const float* sn_w0  = (const float*)d_in[15];
    const float* sn_g0  = (const float*)d_in[16];
    const float* sn_b0  = (const float*)d_in[17];
    const float* sn_w1  = (const float*)d_in[18];
    const float* sn_g1  = (const float*)d_in[19];
    const float* sn_b1  = (const float*)d_in[20];
    const float* sn_w2  = (const float*)d_in[21];
    const float* sn_c2b = (const float*)d_in[22];
    const int*   is_inv = (const int*)d_in[23];

    float* out       = (float*)d_out;
    float* out_depth = out;
    float* out_score = out + (size_t)BB*HWP;
    float* out_vw    = out + (size_t)BB*HWP + (size_t)BB*DD*HWP;

    k_transpose<<<dim3(HWP/64, VV*BB + BB + 1), 256>>>(ref_feature, src_features,
                                                       ref_proj, src_projs);
    k_main<<<BB*HWP/KM_PIX, KM_THREADS>>>(depth_sample,
                              pw_w0, pw_g0, pw_b0, pw_w1, pw_g1, pw_b1, pw_w2, pw_c2b,
                              sn_w0, sn_g0, sn_b0, sn_w1, sn_g1, sn_b1, sn_w2, sn_c2b,
                              out_vw);
    k_final<<<(BB*HWP*4 + 127)/128, 128>>>(grid, weight, depth_sample, is_inv,
                                           out_depth, out_score);
}

// round 15
// speedup vs baseline: 1.1064x; 1.0244x over previous
#include <cuda_runtime.h>
#include <cuda_fp16.h>
#include <math.h>
#include <stdint.h>

#define BB 2
#define CC 64
#define HH 128
#define WW 160
#define DD 16
#define VV 4
#define NV 9
#define HWP (HH*WW)

#define KM_PIX 16                 // pixels per k_main block
#define KM_THREADS (KM_PIX*16)    // 256

// ---------------- scratch (static device memory; no allocation) ----------------
__device__ __align__(16) __half g_srcT[(size_t)VV*BB*HWP*CC]; // fp16 [v*B+b][hw][c]
__device__ __align__(16) __half g_refT[(size_t)BB*HWP*CC];    // fp16 [b][hw][c]
__device__ float g_proj[VV*BB*12];
__device__ __align__(16) float g_s[(size_t)BB*HWP*DD];        // s channels-last [b][hw][d]

#define BNS 0.9999950000374997f

// ---------------- K0: transpose [C,HW] -> [HW,C] (fp32 staging, vectorized) + fused proj ----------------
__global__ void __launch_bounds__(256, 6)
k_transpose(const float* __restrict__ ref, const float* __restrict__ src,
            const float* __restrict__ ref_proj, const float* __restrict__ src_projs) {
    int img = blockIdx.y;          // 0..7 = src v*B+b, 8..9 = ref b, 10 = proj
    if (img == VV*BB + BB) {
        if (blockIdx.x != 0) return;
        int t = threadIdx.x;
        if (t >= VV*BB) return;
        int v = t / BB, b = t % BB;
        float a[4][4], inv[4][4];
        #pragma unroll
        for (int i = 0; i < 4; i++)
            #pragma unroll
            for (int j = 0; j < 4; j++) {
                a[i][j] = ref_proj[b*16 + i*4 + j];
                inv[i][j] = (i == j) ? 1.f : 0.f;
            }
        for (int col = 0; col < 4; col++) {
            int piv = col; float best = fabsf(a[col][col]);
            for (int r = col+1; r < 4; r++) { float av = fabsf(a[r][col]); if (av > best) { best = av; piv = r; } }
            if (piv != col) {
                for (int j = 0; j < 4; j++) {
                    float tm = a[col][j]; a[col][j] = a[piv][j]; a[piv][j] = tm;
                    tm = inv[col][j]; inv[col][j] = inv[piv][j]; inv[piv][j] = tm;
                }
            }
            float dsc = 1.f / a[col][col];
            for (int j = 0; j < 4; j++) { a[col][j] *= dsc; inv[col][j] *= dsc; }
            for (int r = 0; r < 4; r++) {
                if (r == col) continue;
                float f = a[r][col];
                for (int j = 0; j < 4; j++) { a[r][j] -= f*a[col][j]; inv[r][j] -= f*inv[col][j]; }
            }
        }
        const float* s = src_projs + (size_t)(v*BB + b)*16;
        float* o = g_proj + (v*BB + b)*12;
        for (int i = 0; i < 3; i++)
            for (int j = 0; j < 4; j++) {
                float acc = 0.f;
                for (int k = 0; k < 4; k++) acc += s[i*4 + k] * inv[k][j];
                o[i*4 + j] = acc;
            }
        return;
    }
    __shared__ float tile[64][65];
    int hw0 = blockIdx.x * 64;
    int tid = threadIdx.x;
    const float* in = (img < VV*BB) ? (src + (size_t)img*CC*HWP)
                                    : (ref + (size_t)(img - VV*BB)*CC*HWP);
    #pragma unroll
    for (int k = tid; k < 1024; k += 256) {
        int c   = k >> 4;
        int hw4 = k & 15;
        float4 v = *(const float4*)(in + (size_t)c*HWP + hw0 + hw4*4);
        tile[hw4*4+0][c] = v.x;
        tile[hw4*4+1][c] = v.y;
        tile[hw4*4+2][c] = v.z;
        tile[hw4*4+3][c] = v.w;
    }
    __syncthreads();
    __half* outh = (img < VV*BB)
        ? (g_srcT + (size_t)img*HWP*CC)
        : (g_refT + (size_t)(img - VV*BB)*HWP*CC);
    #pragma unroll
    for (int k = tid; k < 1024; k += 256) {
        int hwl = k >> 4;
        int cp4 = k & 15;
        const float* tr = &tile[hwl][cp4*4];
        __half2 p0 = __floats2half2_rn(tr[0], tr[1]);
        __half2 p1 = __floats2half2_rn(tr[2], tr[3]);
        uint2 val = make_uint2(*reinterpret_cast<uint32_t*>(&p0),
                               *reinterpret_cast<uint32_t*>(&p1));
        *(uint2*)(outh + (size_t)(hw0+hwl)*CC + cp4*4) = val;
    }
}

// ---------------- tensor-core helpers ----------------
__device__ __forceinline__ __half2 u2h(uint32_t u) { return *reinterpret_cast<__half2*>(&u); }
__device__ __forceinline__ uint32_t h2u(__half2 h) { return *reinterpret_cast<uint32_t*>(&h); }

__device__ __forceinline__ void ldmatrix_x4(uint32_t& r0, uint32_t& r1, uint32_t& r2, uint32_t& r3,
                                            uint32_t addr) {
    asm volatile("ldmatrix.sync.aligned.m8n8.x4.shared.b16 {%0,%1,%2,%3}, [%4];"
                 : "=r"(r0), "=r"(r1), "=r"(r2), "=r"(r3) : "r"(addr));
}

__device__ __forceinline__ void mma_16n8k8(float d[4], uint32_t a0, uint32_t a1, uint32_t b0) {
    float z = 0.f;
    asm volatile("mma.sync.aligned.m16n8k8.row.col.f32.f16.f16.f32 "
                 "{%0,%1,%2,%3},{%4,%5},{%6},{%7,%8,%9,%10};"
                 : "=f"(d[0]), "=f"(d[1]), "=f"(d[2]), "=f"(d[3])
                 : "r"(a0), "r"(a1), "r"(b0), "f"(z), "f"(z), "f"(z), "f"(z));
}

__device__ __forceinline__ void mma_16n8k16(float d[4], uint32_t a0, uint32_t a1, uint32_t a2, uint32_t a3,
                                            uint32_t b0, uint32_t b1) {
    float z = 0.f;
    asm volatile("mma.sync.aligned.m16n8k16.row.col.f32.f16.f16.f32 "
                 "{%0,%1,%2,%3},{%4,%5,%6,%7},{%8,%9},{%10,%11,%12,%13};"
                 : "=f"(d[0]), "=f"(d[1]), "=f"(d[2]), "=f"(d[3])
                 : "r"(a0), "r"(a1), "r"(a2), "r"(a3), "r"(b0), "r"(b1),
                   "f"(z), "f"(z), "f"(z), "f"(z));
}

// warp-cooperative MLP: 32 samples (rows) x 8 inputs -> per-row scalar output.
__device__ __forceinline__ void mlp_tc(const float* __restrict__ P,
                                       uint32_t bL1n0, uint32_t bL1n1,
                                       uint32_t bL2k0, uint32_t bL2k1,
                                       uint32_t lmaddr, int c2v, float o[2][2]) {
    uint32_t A0, A1, A2, A3;
    ldmatrix_x4(A0, A1, A2, A3, lmaddr);
    float gj0a = P[128 + c2v],     gj1a = P[128 + c2v + 1];
    float gj0b = P[128 + c2v + 8], gj1b = P[128 + c2v + 9];
    float bj0a = P[144 + c2v],     bj1a = P[144 + c2v + 1];
    float bj0b = P[144 + c2v + 8], bj1b = P[144 + c2v + 9];
    float gn0 = P[288 + c2v], gn1 = P[288 + c2v + 1];
    float bn0 = P[296 + c2v], bn1 = P[296 + c2v + 1];
    float w2a = P[304 + c2v], w2b = P[304 + c2v + 1];
    float c2b = P[312];
    #pragma unroll
    for (int m = 0; m < 2; m++) {
        uint32_t a0 = m ? A2 : A0, a1 = m ? A3 : A1;
        float d0[4], d1[4];
        mma_16n8k8(d0, a0, a1, bL1n0);
        mma_16n8k8(d1, a0, a1, bL1n1);
        float h00 = fmaxf(0.f, d0[0]*gj0a + bj0a), h01 = fmaxf(0.f, d0[1]*gj1a + bj1a);
        float h02 = fmaxf(0.f, d0[2]*gj0a + bj0a), h03 = fmaxf(0.f, d0[3]*gj1a + bj1a);
        float h10 = fmaxf(0.f, d1[0]*gj0b + bj0b), h11 = fmaxf(0.f, d1[1]*gj1b + bj1b);
        float h12 = fmaxf(0.f, d1[2]*gj0b + bj0b), h13 = fmaxf(0.f, d1[3]*gj1b + bj1b);
        uint32_t e0 = h2u(__floats2half2_rn(h00, h01));
        uint32_t e1 = h2u(__floats2half2_rn(h02, h03));
        uint32_t e2 = h2u(__floats2half2_rn(h10, h11));
        uint32_t e3 = h2u(__floats2half2_rn(h12, h13));
        float d2[4];
        mma_16n8k16(d2, e0, e1, e2, e3, bL2k0, bL2k1);
        float f0 = fmaxf(0.f, d2[0]*gn0 + bn0), f1 = fmaxf(0.f, d2[1]*gn1 + bn1);
        float f2 = fmaxf(0.f, d2[2]*gn0 + bn0), f3 = fmaxf(0.f, d2[3]*gn1 + bn1);
        float p0 = w2a*f0 + w2b*f1;
        float p1 = w2a*f2 + w2b*f3;
        p0 += __shfl_xor_sync(0xffffffffu, p0, 1);
        p0 += __shfl_xor_sync(0xffffffffu, p0, 2);
        p1 += __shfl_xor_sync(0xffffffffu, p1, 1);
        p1 += __shfl_xor_sync(0xffffffffu, p1, 2);
        o[m][0] = p0 + c2b;
        o[m][1] = p1 + c2b;
    }
}

// ---------------- K2: warp + group correlation + tensor-core MLPs ----------------
// block = 256 threads = 16 pixels × 16 lanes; warp covers 2 pixels (32 samples).
// Phase A hoisted: coords for ALL views computed once into scoord[pix][d][view].
#define SIMS 24   // simh row stride in halves (48B)
#define SCW 20    // scoord stride in words per (pix,d): 4 views × uint4 + pad
__global__ void __launch_bounds__(KM_THREADS)
k_main(const float* __restrict__ depth_sample,
       const float* __restrict__ pw_w0, const float* __restrict__ pw_g0, const float* __restrict__ pw_b0,
       const float* __restrict__ pw_w1, const float* __restrict__ pw_g1, const float* __restrict__ pw_b1,
       const float* __restrict__ pw_w2, const float* __restrict__ pw_c2b,
       const float* __restrict__ sn_w0, const float* __restrict__ sn_g0, const float* __restrict__ sn_b0,
       const float* __restrict__ sn_w1, const float* __restrict__ sn_g1, const float* __restrict__ sn_b1,
       const float* __restrict__ sn_w2, const float* __restrict__ sn_c2b,
       float* __restrict__ out_vw) {
    __shared__ float sfp[2][320];
    __shared__ __align__(16) uint32_t scoord[KM_PIX*16*SCW];
    __shared__ __align__(16) __half simh[KM_PIX*16*SIMS];

    int tid = threadIdx.x;

    for (int i = tid; i < 640; i += KM_THREADS) {
        int net = i / 320, j = i - net*320;
        const float* w0 = net ? sn_w0 : pw_w0;
        const float* g0 = net ? sn_g0 : pw_g0;
        const float* b0 = net ? sn_b0 : pw_b0;
        const float* w1 = net ? sn_w1 : pw_w1;
        const float* g1 = net ? sn_g1 : pw_g1;
        const float* b1 = net ? sn_b1 : pw_b1;
        const float* w2 = net ? sn_w2 : pw_w2;
        const float* cb = net ? sn_c2b : pw_c2b;
        float val;
        if      (j < 128) val = w0[j];
        else if (j < 144) val = g0[j-128] * BNS;
        else if (j < 160) val = b0[j-144];
        else if (j < 288) val = w1[j-160];
        else if (j < 296) val = g1[j-288] * BNS;
        else if (j < 304) val = b1[j-296];
        else if (j < 312) val = w2[j-304];
        else if (j == 312) val = cb[0];
        else val = 0.f;
        sfp[net][j] = val;
    }
    __syncthreads();

    int l   = tid & 31;
    int q   = l >> 2;
    int c2v = (l & 3) * 2;
    int warpid = tid >> 5;

    uint32_t bw0[2][2], bw1[2][2];
    #pragma unroll
    for (int t = 0; t < 2; t++) {
        const float* P = sfp[t];
        bw0[t][0] = h2u(__floats2half2_rn(P[q*8 + c2v],        P[q*8 + c2v + 1]));
        bw0[t][1] = h2u(__floats2half2_rn(P[(q+8)*8 + c2v],    P[(q+8)*8 + c2v + 1]));
        bw1[t][0] = h2u(__floats2half2_rn(P[160 + q*16 + c2v],     P[160 + q*16 + c2v + 1]));
        bw1[t][1] = h2u(__floats2half2_rn(P[160 + q*16 + 8 + c2v], P[160 + q*16 + 9 + c2v]));
    }

    int pix  = tid >> 4;
    int lane = tid & 15;
    int dh   = lane >> 3;
    int g    = lane & 7;
    int p = blockIdx.x * KM_PIX + pix;
    int b  = p / HWP;
    int hw = p - b * HWP;
    int h = hw / WW, w = hw - h * WW;
    float wf = (float)w, hf = (float)h;

    uint32_t sbase = (uint32_t)__cvta_generic_to_shared(simh);
    uint32_t lmaddr = sbase + (uint32_t)(warpid*32 + l) * (SIMS*2);
    __half* myrow = simh + (warpid*32 + l) * SIMS;

    uint4 ru = __ldg((const uint4*)(g_refT + (size_t)p*CC) + g);
    __half2 rh0 = u2h(ru.x), rh1 = u2h(ru.y), rh2 = u2h(ru.z), rh3 = u2h(ru.w);

    float myDep = __ldg(depth_sample + (size_t)b*DD*HWP + (size_t)lane*HWP + hw);

    // ---- Phase A (all views): coords for owned depth ----
    {
        uint32_t* sc = scoord + (pix*16 + lane)*SCW;
        #pragma unroll
        for (int v = 0; v < VV; v++) {
            const float* M = g_proj + (v*BB + b)*12;
            float rx = M[0]*wf + M[1]*hf + M[2];
            float ry = M[4]*wf + M[5]*hf + M[6];
            float rz = M[8]*wf + M[9]*hf + M[10];
            float px = rx*myDep + M[3], py = ry*myDep + M[7], pz = rz*myDep + M[11];
            if (pz <= 0.001f) { px = (float)WW; py = (float)HH; pz = 1.f; }
            float ix = __fdividef(px, pz);
            float iy = __fdividef(py, pz);
            float x0f = floorf(ix), y0f = floorf(iy);
            float fx = ix - x0f, fy = iy - y0f;
            int x0 = (int)x0f, y0 = (int)y0f;
            int x1 = x0 + 1, y1 = y0 + 1;
            bool vx0 = (x0 >= 0) & (x0 < WW);
            bool vx1 = (x1 >= 0) & (x1 < WW);
            bool vy0 = (y0 >= 0) & (y0 < HH);
            bool vy1 = (y1 >= 0) & (y1 < HH);
            float w00 = (1.f-fx)*(1.f-fy) * (float)(vx0 && vy0);
            float w01 = fx*(1.f-fy)       * (float)(vx1 && vy0);
            float w10 = (1.f-fx)*fy       * (float)(vx0 && vy1);
            float w11 = fx*fy             * (float)(vx1 && vy1);
            int xc0 = min(max(x0, 0), WW-1), xc1 = min(max(x1, 0), WW-1);
            int yc0 = min(max(y0, 0), HH-1), yc1 = min(max(y1, 0), HH-1);
            int r0 = yc0*WW, r1 = yc1*WW;
            uint32_t i00 = (uint32_t)(r0 + xc0), i01 = (uint32_t)(r0 + xc1);
            uint32_t i10 = (uint32_t)(r1 + xc0), i11 = (uint32_t)(r1 + xc1);
            __half2 hw01 = __floats2half2_rn(w00, w01);
            __half2 hw23 = __floats2half2_rn(w10, w11);
            *(uint4*)&sc[v*4] = make_uint4(i00 | (i01 << 16), i10 | (i11 << 16),
                                           h2u(hw01), h2u(hw23));
        }
    }
    __syncwarp();

    float acc[8];
    #pragma unroll
    for (int k = 0; k < 8; k++) acc[k] = 0.f;
    float wsum = 0.f;

    for (int v = 0; v < VV; v++) {
        const __half* srcB = g_srcT + (size_t)(v*BB + b)*HWP*CC;

        // ---- Phase B: 8 depths per lane ----
        #pragma unroll
        for (int dl = 0; dl < 8; dl++) {
            int d = dh*8 + dl;
            uint4 cw = *(const uint4*)&scoord[(pix*16 + d)*SCW + v*4];
            uint32_t i00 = cw.x & 0xFFFFu, i01 = cw.x >> 16;
            uint32_t i10 = cw.y & 0xFFFFu, i11 = cw.y >> 16;
            __half2 pw01 = u2h(cw.z), pw23 = u2h(cw.w);
            __half2 w00 = __low2half2(pw01),  w01 = __high2half2(pw01);
            __half2 w10 = __low2half2(pw23),  w11 = __high2half2(pw23);
            uint4 u00 = __ldg((const uint4*)(srcB + (size_t)i00*CC) + g);
            uint4 u01 = __ldg((const uint4*)(srcB + (size_t)i01*CC) + g);
            uint4 u10 = __ldg((const uint4*)(srcB + (size_t)i10*CC) + g);
            uint4 u11 = __ldg((const uint4*)(srcB + (size_t)i11*CC) + g);
            __half2 m0 = __hmul2(u2h(u00.x), w00);
            __half2 m1 = __hmul2(u2h(u00.y), w00);
            __half2 m2 = __hmul2(u2h(u00.z), w00);
            __half2 m3 = __hmul2(u2h(u00.w), w00);
            m0 = __hfma2(u2h(u01.x), w01, m0);
            m1 = __hfma2(u2h(u01.y), w01, m1);
            m2 = __hfma2(u2h(u01.z), w01, m2);
            m3 = __hfma2(u2h(u01.w), w01, m3);
            m0 = __hfma2(u2h(u10.x), w10, m0);
            m1 = __hfma2(u2h(u10.y), w10, m1);
            m2 = __hfma2(u2h(u10.z), w10, m2);
            m3 = __hfma2(u2h(u10.w), w10, m3);
            m0 = __hfma2(u2h(u11.x), w11, m0);
            m1 = __hfma2(u2h(u11.y), w11, m1);
            m2 = __hfma2(u2h(u11.z), w11, m2);
            m3 = __hfma2(u2h(u11.w), w11, m3);
            __half2 da = __hmul2(m0, rh0);
            da = __hfma2(m1, rh1, da);
            da = __hfma2(m2, rh2, da);
            da = __hfma2(m3, rh3, da);
            float2 df = __half22float2(da);
            simh[(pix*16 + d)*SIMS + g] = __float2half_rn((df.x + df.y) * 0.125f);
        }
        __syncwarp();

        // ---- pixelwise net (tensor cores) ----
        float o[2][2];
        mlp_tc(sfp[0], bw0[0][0], bw0[0][1], bw1[0][0], bw1[0][1], lmaddr, c2v, o);

        float m0 = fmaxf(o[0][0], o[0][1]);
        float m1 = fmaxf(o[1][0], o[1][1]);
        m0 = fmaxf(m0, __shfl_xor_sync(0xffffffffu, m0, 4));
        m1 = fmaxf(m1, __shfl_xor_sync(0xffffffffu, m1, 4));
        m0 = fmaxf(m0, __shfl_xor_sync(0xffffffffu, m0, 8));
        m1 = fmaxf(m1, __shfl_xor_sync(0xffffffffu, m1, 8));
        m0 = fmaxf(m0, __shfl_xor_sync(0xffffffffu, m0, 16));
        m1 = fmaxf(m1, __shfl_xor_sync(0xffffffffu, m1, 16));
        float omax = (l & 16) ? m1 : m0;
        float vwv = __frcp_rn(1.f + __expf(-omax));

        if (lane == 0) out_vw[((size_t)b*VV + v)*HWP + hw] = vwv;

        uint4 sv = *(const uint4*)myrow;
        float2 a0 = __half22float2(u2h(sv.x));
        float2 a1 = __half22float2(u2h(sv.y));
        float2 a2 = __half22float2(u2h(sv.z));
        float2 a3 = __half22float2(u2h(sv.w));
        acc[0] += a0.x*vwv; acc[1] += a0.y*vwv; acc[2] += a1.x*vwv; acc[3] += a1.y*vwv;
        acc[4] += a2.x*vwv; acc[5] += a2.y*vwv; acc[6] += a3.x*vwv; acc[7] += a3.y*vwv;
        wsum += vwv;
        __syncwarp();
    }

    // ---- similarity net ----
    float rws = 1.f / wsum;
    {
        __half2 s0 = __floats2half2_rn(acc[0]*rws, acc[1]*rws);
        __half2 s1 = __floats2half2_rn(acc[2]*rws, acc[3]*rws);
        __half2 s2 = __floats2half2_rn(acc[4]*rws, acc[5]*rws);
        __half2 s3 = __floats2half2_rn(acc[6]*rws, acc[7]*rws);
        *(uint4*)myrow = make_uint4(h2u(s0), h2u(s1), h2u(s2), h2u(s3));
    }
    __syncwarp();
    float o2[2][2];
    mlp_tc(sfp[1], bw0[1][0], bw0[1][1], bw1[1][0], bw1[1][1], lmaddr, c2v, o2);

    if ((l & 3) == 0) {
        int pbase = blockIdx.x * KM_PIX + 2*warpid;
        g_s[(size_t)pbase*DD + q]          = o2[0][0];
        g_s[(size_t)pbase*DD + q + 8]      = o2[0][1];
        g_s[(size_t)(pbase+1)*DD + q]      = o2[1][0];
        g_s[(size_t)(pbase+1)*DD + q + 8]  = o2[1][1];
    }
}

// ---------------- K3: grid-sample + NN aggregation + softmax + depth ----------------
__global__ void __launch_bounds__(128)
k_final(const float* __restrict__ grid, const float* __restrict__ weight,
        const float* __restrict__ depth_sample, const int* __restrict__ is_inverse,
        float* __restrict__ out_depth, float* __restrict__ out_score) {
    int t = blockIdx.x * blockDim.x + threadIdx.x;
    int p = t >> 2;
    int q = t & 3;
    if (p >= BB*HWP) return;
    int b  = p / HWP;
    int hw = p - b * HWP;
    int h = hw / WW, w = hw - h * WW;

    float agg[4] = {0.f, 0.f, 0.f, 0.f};

    const float* wbase = weight + ((size_t)b*DD*NV)*HWP + hw + (size_t)(q*4)*NV*HWP;
    #pragma unroll
    for (int n = 0; n < NV; n++) {
        const float* gp = grid + (((size_t)b*NV*HH + n*HH + h)*WW + w)*2;
        float gx = __ldg(gp), gy = __ldg(gp + 1);
        float ix = ((gx + 1.f)*WW - 1.f) * 0.5f;
        float iy = ((gy + 1.f)*HH - 1.f) * 0.5f;
        float x0f = floorf(ix), y0f = floorf(iy);
        float fx = ix - x0f, fy = iy - y0f;
        int x0 = (int)x0f, y0 = (int)y0f;
        int xc0 = min(max(x0, 0), WW-1), xc1 = min(max(x0+1, 0), WW-1);
        int yc0 = min(max(y0, 0), HH-1), yc1 = min(max(y0+1, 0), HH-1);
        float w00 = (1.f-fx)*(1.f-fy), w01 = fx*(1.f-fy);
        float w10 = (1.f-fx)*fy,       w11 = fx*fy;
        float4 a00 = __ldg((const float4*)(g_s + ((size_t)b*HWP + yc0*WW + xc0)*DD) + q);
        float4 a01 = __ldg((const float4*)(g_s + ((size_t)b*HWP + yc0*WW + xc1)*DD) + q);
        float4 a10 = __ldg((const float4*)(g_s + ((size_t)b*HWP + yc1*WW + xc0)*DD) + q);
        float4 a11 = __ldg((const float4*)(g_s + ((size_t)b*HWP + yc1*WW + xc1)*DD) + q);
        float bx = w00*a00.x + w01*a01.x + w10*a10.x + w11*a11.x;
        float by = w00*a00.y + w01*a01.y + w10*a10.y + w11*a11.y;
        float bz = w00*a00.z + w01*a01.z + w10*a10.z + w11*a11.z;
        float bw = w00*a00.w + w01*a01.w + w10*a10.w + w11*a11.w;
        const float* wb = wbase + (size_t)n*HWP;
        agg[0] += __ldg(wb)                      * bx;
        agg[1] += __ldg(wb + (size_t)1*NV*HWP)   * by;
        agg[2] += __ldg(wb + (size_t)2*NV*HWP)   * bz;
        agg[3] += __ldg(wb + (size_t)3*NV*HWP)   * bw;
    }

    float m = fmaxf(fmaxf(agg[0], agg[1]), fmaxf(agg[2], agg[3]));
    m = fmaxf(m, __shfl_xor_sync(0xffffffffu, m, 1, 4));
    m = fmaxf(m, __shfl_xor_sync(0xffffffffu, m, 2, 4));
    float e[4]; float sum = 0.f;
    #pragma unroll
    for (int j = 0; j < 4; j++) { e[j] = __expf(agg[j] - m); sum += e[j]; }
    sum += __shfl_xor_sync(0xffffffffu, sum, 1, 4);
    sum += __shfl_xor_sync(0xffffffffu, sum, 2, 4);
    float rs = 1.f / sum;

    const float* dsB = depth_sample + (size_t)b*DD*HWP + hw;
    float dep = 0.f;
    int inv = *is_inverse;
    #pragma unroll
    for (int j = 0; j < 4; j++) {
        float sc = e[j] * rs;
        int d = q*4 + j;
        out_score[((size_t)b*DD + d)*HWP + hw] = sc;
        if (inv) dep += (float)d * sc;
        else     dep += __ldg(dsB + (size_t)d*HWP) * sc;
    }
    dep += __shfl_xor_sync(0xffffffffu, dep, 1, 4);
    dep += __shfl_xor_sync(0xffffffffu, dep, 2, 4);
    if (q == 0) {
        if (inv) {
            float invmin = 1.f / __ldg(dsB + (size_t)(DD-1)*HWP);
            float invmax = 1.f / __ldg(dsB);
            dep = 1.f / (invmax + dep * (1.f/(float)(DD-1)) * (invmin - invmax));
        }
        out_depth[p] = dep;
    }
}

// ---------------- launch ----------------
extern "C" void kernel_launch(void* const* d_in, const int* in_sizes, int n_in,
                              void* d_out, int out_size) {
    const float* ref_feature  = (const float*)d_in[0];
    const float* src_features = (const float*)d_in[1];
    const float* ref_proj     = (const float*)d_in[2];
    const float* src_projs    = (const float*)d_in[3];
    const float* depth_sample = (const float*)d_in[4];
    const float* grid         = (const float*)d_in[5];
    const float* weight       = (const float*)d_in[6];
    const float* pw_w0  = (const float*)d_in[7];
    const float* pw_g0  = (const float*)d_in[8];
    const float* pw_b0  = (const float*)d_in[9];
    const float* pw_w1  = (const float*)d_in[10];
    const float* pw_g1  = (const float*)d_in[11];
    const float* pw_b1  = (const float*)d_in[12];
    const float* pw_w2  = (const float*)d_in[13];
    const float* pw_c2b = (const float*)d_in[14];
    const float* sn_w0  = (const float*)d_in[15];
    const float* sn_g0  = (const float*)d_in[16];
    const float* sn_b0  = (const float*)d_in[17];
    const float* sn_w1  = (const float*)d_in[18];
    const float* sn_g1  = (const float*)d_in[19];
    const float* sn_b1  = (const float*)d_in[20];
    const float* sn_w2  = (const float*)d_in[21];
    const float* sn_c2b = (const float*)d_in[22];
    const int*   is_inv = (const int*)d_in[23];

    float* out       = (float*)d_out;
    float* out_depth = out;
    float* out_score = out + (size_t)BB*HWP;
    float* out_vw    = out + (size_t)BB*HWP + (size_t)BB*DD*HWP;

    k_transpose<<<dim3(HWP/64, VV*BB + BB + 1), 256>>>(ref_feature, src_features,
                                                       ref_proj, src_projs);
    k_main<<<BB*HWP/KM_PIX, KM_THREADS>>>(depth_sample,
                              pw_w0, pw_g0, pw_b0, pw_w1, pw_g1, pw_b1, pw_w2, pw_c2b,
                              sn_w0, sn_g0, sn_b0, sn_w1, sn_g1, sn_b1, sn_w2, sn_c2b,
                              out_vw);
    k_final<<<(BB*HWP*4 + 127)/128, 128>>>(grid, weight, depth_sample, is_inv,
                                           out_depth, out_score);
}